// round 1
// baseline (speedup 1.0000x reference)
#include <cuda_runtime.h>
#include <math.h>

// ---------------------------------------------------------------------------
// Problem constants
// ---------------------------------------------------------------------------
#define BATCH   4
#define NTOK    4096
#define INCH    1280
#define CDIM    256          // IN_CH / DIM_DOWN
#define QKVD    768          // 3*CDIM
#define HEADS   8
#define HD      32           // CDIM / HEADS
#define CUT     4
#define BLKTOK  1024         // NTOK / CUT
#define M_TOTAL (BATCH*NTOK) // 16384
#define SCALE_F 0.07905694150420949f   // (1280/8)^-0.5 = 160^-0.5

// ---------------------------------------------------------------------------
// Scratch (no cudaMalloc allowed): h, qkv, o intermediates
// ---------------------------------------------------------------------------
__device__ float g_h[M_TOTAL * CDIM];     // 16.8 MB
__device__ float g_qkv[M_TOTAL * QKVD];   // 50.3 MB
__device__ float g_o[M_TOTAL * CDIM];     // 16.8 MB

// ---------------------------------------------------------------------------
// Tiled fp32 GEMM: C[M,N] = A[M,K] @ B[K,N] (+ bias[n] if bias != nullptr)
// 128x128 block tile, 256 threads, 8x8 per thread, K-tile = 16.
// M % 128 == 0, N % 128 == 0, K % 16 == 0 (all true for our shapes).
// ---------------------------------------------------------------------------
__global__ void __launch_bounds__(256)
gemm_tiled(const float* __restrict__ A, const float* __restrict__ B,
           const float* __restrict__ bias, float* __restrict__ C,
           int M, int N, int K)
{
    __shared__ float As[16][129];   // transposed A tile: As[k][m]
    __shared__ float Bs[16][132];   // Bs[k][n]

    const int tid = threadIdx.x;
    const int tx  = tid & 15;   // N direction (8 cols each)
    const int ty  = tid >> 4;   // M direction (8 rows each)
    const int rowBase = blockIdx.y * 128;
    const int colBase = blockIdx.x * 128;

    float acc[8][8];
#pragma unroll
    for (int i = 0; i < 8; i++)
#pragma unroll
        for (int j = 0; j < 8; j++) acc[i][j] = 0.0f;

    // load-index precompute
    const int aRow  = tid >> 2;        // 0..63 (two passes -> 128 rows)
    const int aCol4 = (tid & 3) * 4;   // 0,4,8,12
    const int bRow  = tid >> 5;        // 0..7 (two passes -> 16 rows)
    const int bCol4 = (tid & 31) * 4;  // 0..124

    for (int kt = 0; kt < K; kt += 16) {
        // ---- load A tile (128 x 16), store transposed into As[k][m]
#pragma unroll
        for (int rr = 0; rr < 2; rr++) {
            const int r = aRow + rr * 64;
            float4 av = *(const float4*)&A[(size_t)(rowBase + r) * K + kt + aCol4];
            As[aCol4 + 0][r] = av.x;
            As[aCol4 + 1][r] = av.y;
            As[aCol4 + 2][r] = av.z;
            As[aCol4 + 3][r] = av.w;
        }
        // ---- load B tile (16 x 128)
#pragma unroll
        for (int rr = 0; rr < 2; rr++) {
            const int r = bRow + rr * 8;
            float4 bv = *(const float4*)&B[(size_t)(kt + r) * N + colBase + bCol4];
            *(float4*)&Bs[r][bCol4] = bv;
        }
        __syncthreads();

#pragma unroll
        for (int k = 0; k < 16; k++) {
            float a[8], b[8];
#pragma unroll
            for (int i = 0; i < 8; i++) a[i] = As[k][ty * 8 + i];
            float4 b0 = *(float4*)&Bs[k][tx * 8];
            float4 b1 = *(float4*)&Bs[k][tx * 8 + 4];
            b[0] = b0.x; b[1] = b0.y; b[2] = b0.z; b[3] = b0.w;
            b[4] = b1.x; b[5] = b1.y; b[6] = b1.z; b[7] = b1.w;
#pragma unroll
            for (int i = 0; i < 8; i++)
#pragma unroll
                for (int j = 0; j < 8; j++)
                    acc[i][j] = fmaf(a[i], b[j], acc[i][j]);
        }
        __syncthreads();
    }

    // ---- epilogue
#pragma unroll
    for (int i = 0; i < 8; i++) {
        const int row = rowBase + ty * 8 + i;
#pragma unroll
        for (int j = 0; j < 8; j += 4) {
            const int col = colBase + tx * 8 + j;
            float4 v;
            v.x = acc[i][j + 0];
            v.y = acc[i][j + 1];
            v.z = acc[i][j + 2];
            v.w = acc[i][j + 3];
            if (bias) {
                v.x += bias[col + 0];
                v.y += bias[col + 1];
                v.z += bias[col + 2];
                v.w += bias[col + 3];
            }
            *(float4*)&C[(size_t)row * N + col] = v;
        }
    }
}

// ---------------------------------------------------------------------------
// Block-local attention with online softmax.
// Grid: BATCH*HEADS*CUT*(BLKTOK/64) = 2048 CTAs, 256 threads each.
// CTA handles 64 query rows for one (b, h, chunk). Loops over 16 key tiles
// of 64. Thread (r = tid>>2, t = tid&3): scores split over keys (t picks 16
// of 64 keys); output accumulation split over d (t picks 8 of 32 dims).
// ---------------------------------------------------------------------------
__global__ void __launch_bounds__(256)
attn_kernel(const float* __restrict__ qkv, float* __restrict__ o_out)
{
    __shared__ float sk[64][36];
    __shared__ float sv[64][36];
    __shared__ float sp[64][68];

    const int bi = blockIdx.x;
    const int qt = bi & 15;          // query tile within chunk
    const int c  = (bi >> 4) & 3;    // chunk
    const int h  = (bi >> 6) & 7;    // head
    const int b  = bi >> 9;          // batch

    const int tid = threadIdx.x;
    const int r = tid >> 2;          // query row within tile (0..63)
    const int t = tid & 3;           // key-split / d-split part (0..3)

    const int qrow = c * BLKTOK + qt * 64 + r;   // token index in [0,NTOK)
    const float* qptr = qkv + ((size_t)(b * NTOK + qrow)) * QKVD + h * HD;

    // q row into registers, pre-scaled
    float qreg[32];
#pragma unroll
    for (int d = 0; d < 32; d += 4) {
        float4 v = *(const float4*)(qptr + d);
        qreg[d + 0] = v.x * SCALE_F;
        qreg[d + 1] = v.y * SCALE_F;
        qreg[d + 2] = v.z * SCALE_F;
        qreg[d + 3] = v.w * SCALE_F;
    }

    float m = -1e30f, l = 0.0f;
    float oacc[8];
#pragma unroll
    for (int dd = 0; dd < 8; dd++) oacc[dd] = 0.0f;

    const int ldRow = tid >> 3;        // 0..31 (two passes -> 64 rows)
    const int ldCol = (tid & 7) * 4;   // 0..28

    const int kTokBase = c * BLKTOK;

    for (int kt = 0; kt < 16; kt++) {
        // ---- load K and V tiles (64 x 32 each)
#pragma unroll
        for (int rr = 0; rr < 2; rr++) {
            const int kr  = ldRow + rr * 32;
            const int tok = kTokBase + kt * 64 + kr;
            const float* base = qkv + ((size_t)(b * NTOK + tok)) * QKVD + h * HD;
            float4 kv = *(const float4*)(base + CDIM + ldCol);      // K at +256
            float4 vv = *(const float4*)(base + 2 * CDIM + ldCol);  // V at +512
            *(float4*)&sk[kr][ldCol] = kv;
            *(float4*)&sv[kr][ldCol] = vv;
        }
        __syncthreads();

        // ---- scores for my 16 keys: j = t*16 + jj
        float s[16];
#pragma unroll
        for (int jj = 0; jj < 16; jj++) {
            const float* krow = &sk[t * 16 + jj][0];
            float a = 0.0f;
#pragma unroll
            for (int d4 = 0; d4 < 32; d4 += 4) {
                float4 kv = *(const float4*)(krow + d4);
                a = fmaf(qreg[d4 + 0], kv.x, a);
                a = fmaf(qreg[d4 + 1], kv.y, a);
                a = fmaf(qreg[d4 + 2], kv.z, a);
                a = fmaf(qreg[d4 + 3], kv.w, a);
            }
            s[jj] = a;
        }

        // ---- online softmax (4-lane group = one query row)
        float mloc = s[0];
#pragma unroll
        for (int jj = 1; jj < 16; jj++) mloc = fmaxf(mloc, s[jj]);
        mloc = fmaxf(mloc, __shfl_xor_sync(0xffffffffu, mloc, 1));
        mloc = fmaxf(mloc, __shfl_xor_sync(0xffffffffu, mloc, 2));
        const float newm = fmaxf(m, mloc);
        const float alpha = __expf(m - newm);
        float lsum = 0.0f;
#pragma unroll
        for (int jj = 0; jj < 16; jj++) {
            const float p = __expf(s[jj] - newm);
            s[jj] = p;
            lsum += p;
        }
        lsum += __shfl_xor_sync(0xffffffffu, lsum, 1);
        lsum += __shfl_xor_sync(0xffffffffu, lsum, 2);
        l = l * alpha + lsum;
        m = newm;
#pragma unroll
        for (int dd = 0; dd < 8; dd++) oacc[dd] *= alpha;

        // ---- exchange P through smem, then accumulate O over all 64 keys
#pragma unroll
        for (int jj = 0; jj < 16; jj++) sp[r][t * 16 + jj] = s[jj];
        __syncthreads();

#pragma unroll 8
        for (int j = 0; j < 64; j++) {
            const float p = sp[r][j];
            const float* vrow = &sv[j][t * 8];
            float4 v0 = *(const float4*)(vrow);
            float4 v1 = *(const float4*)(vrow + 4);
            oacc[0] = fmaf(p, v0.x, oacc[0]);
            oacc[1] = fmaf(p, v0.y, oacc[1]);
            oacc[2] = fmaf(p, v0.z, oacc[2]);
            oacc[3] = fmaf(p, v0.w, oacc[3]);
            oacc[4] = fmaf(p, v1.x, oacc[4]);
            oacc[5] = fmaf(p, v1.y, oacc[5]);
            oacc[6] = fmaf(p, v1.z, oacc[6]);
            oacc[7] = fmaf(p, v1.w, oacc[7]);
        }
        __syncthreads();
    }

    // ---- normalize and write out: o[b, n, h*32 + t*8 + dd]
    const float inv = 1.0f / l;
    float* optr = o_out + ((size_t)(b * NTOK + qrow)) * CDIM + h * HD + t * 8;
    float4 o0, o1;
    o0.x = oacc[0] * inv; o0.y = oacc[1] * inv;
    o0.z = oacc[2] * inv; o0.w = oacc[3] * inv;
    o1.x = oacc[4] * inv; o1.y = oacc[5] * inv;
    o1.z = oacc[6] * inv; o1.w = oacc[7] * inv;
    *(float4*)(optr + 0) = o0;
    *(float4*)(optr + 4) = o1;
}

// ---------------------------------------------------------------------------
// Launch
// ---------------------------------------------------------------------------
extern "C" void kernel_launch(void* const* d_in, const int* in_sizes, int n_in,
                              void* d_out, int out_size)
{
    const float* x    = (const float*)d_in[0];   // [4,4096,1280]
    const float* Wd   = (const float*)d_in[1];   // [1280,256]
    const float* Wqkv = (const float*)d_in[2];   // [256,768]
    const float* Wup  = (const float*)d_in[3];   // [256,1280]
    const float* bup  = (const float*)d_in[4];   // [1280]
    float* out = (float*)d_out;                  // [4,4096,1280]

    float *ph, *pqkv, *po;
    cudaGetSymbolAddress((void**)&ph,   g_h);
    cudaGetSymbolAddress((void**)&pqkv, g_qkv);
    cudaGetSymbolAddress((void**)&po,   g_o);

    // GEMM1: h = x @ Wd            [16384,1280] x [1280,256]
    {
        dim3 grid(CDIM / 128, M_TOTAL / 128);
        gemm_tiled<<<grid, 256>>>(x, Wd, nullptr, ph, M_TOTAL, CDIM, INCH);
    }
    // GEMM2: qkv = h @ Wqkv        [16384,256] x [256,768]
    {
        dim3 grid(QKVD / 128, M_TOTAL / 128);
        gemm_tiled<<<grid, 256>>>(ph, Wqkv, nullptr, pqkv, M_TOTAL, QKVD, CDIM);
    }
    // Attention: 2048 CTAs
    {
        attn_kernel<<<BATCH * HEADS * CUT * (BLKTOK / 64), 256>>>(pqkv, po);
    }
    // GEMM3: out = o @ Wup + bup   [16384,256] x [256,1280]
    {
        dim3 grid(INCH / 128, M_TOTAL / 128);
        gemm_tiled<<<grid, 256>>>(po, Wup, bup, out, M_TOTAL, INCH, CDIM);
    }
}

// round 3
// speedup vs baseline: 5.7375x; 5.7375x over previous
#include <cuda_runtime.h>
#include <stdint.h>
#include <math.h>

// ---------------------------------------------------------------------------
// Problem constants
// ---------------------------------------------------------------------------
#define BATCH   4
#define NTOK    4096
#define INCH    1280
#define CDIM    256
#define QKVD    768
#define HEADS   8
#define HD      32
#define CUT     4
#define BLKTOK  1024
#define M_TOTAL (BATCH*NTOK)
#define SCALE_F 0.07905694150420949f   // 160^-0.5

// ---------------------------------------------------------------------------
// Scratch
// ---------------------------------------------------------------------------
__device__ float g_h[M_TOTAL * CDIM];
__device__ float g_qkv[M_TOTAL * QKVD];
__device__ float g_o[M_TOTAL * CDIM];

// ---------------------------------------------------------------------------
// tf32 helpers (arch-portable PTX; works on plain sm_103 target)
// ---------------------------------------------------------------------------
__device__ __forceinline__ uint32_t tf32r(float x) {
    uint32_t u;
    asm("cvt.rna.tf32.f32 %0, %1;" : "=r"(u) : "f"(x));
    return u;
}

__device__ __forceinline__ void mma_tf32(float* d, const uint32_t* a, const uint32_t* b) {
    asm volatile(
        "mma.sync.aligned.m16n8k8.row.col.f32.tf32.tf32.f32 "
        "{%0,%1,%2,%3}, {%4,%5,%6,%7}, {%8,%9}, {%0,%1,%2,%3};"
        : "+f"(d[0]), "+f"(d[1]), "+f"(d[2]), "+f"(d[3])
        : "r"(a[0]), "r"(a[1]), "r"(a[2]), "r"(a[3]), "r"(b[0]), "r"(b[1]));
}

// ---------------------------------------------------------------------------
// Tensor-core tf32 GEMM: C[M,N] = A[M,K] @ B[K,N] (+bias)
// CTA tile 128x128, 8 warps (2x4), warp tile 64x32, K staged 32.
// A smem [128][36] (tf32), B smem [32][136] (tf32). Conflict-free frag reads.
// ---------------------------------------------------------------------------
__global__ void __launch_bounds__(256)
gemm_mma(const float* __restrict__ A, const float* __restrict__ B,
         const float* __restrict__ bias, float* __restrict__ C,
         int M, int N, int K)
{
    __shared__ uint32_t As[128][36];
    __shared__ uint32_t Bs[32][136];

    const int tid  = threadIdx.x;
    const int wid  = tid >> 5;
    const int lane = tid & 31;
    const int gid  = lane >> 2;   // group id 0..7
    const int tig  = lane & 3;    // thread in group 0..3
    const int wm   = wid >> 2;    // 0..1  (M dir, 64 each)
    const int wn   = wid & 3;     // 0..3  (N dir, 32 each)
    const int rowBase = blockIdx.y * 128;
    const int colBase = blockIdx.x * 128;

    float acc[4][4][4];           // [mi][ni][reg]
#pragma unroll
    for (int mi = 0; mi < 4; mi++)
#pragma unroll
        for (int ni = 0; ni < 4; ni++)
#pragma unroll
            for (int r = 0; r < 4; r++) acc[mi][ni][r] = 0.0f;

    // load indices
    const int aRow = tid >> 3;          // 0..31, 4 iters -> 128 rows
    const int aC4  = (tid & 7) * 4;     // 0..28
    const int bRow = tid >> 5;          // 0..7, 4 iters -> 32 rows
    const int bC4  = (tid & 31) * 4;    // 0..124

    for (int kt = 0; kt < K; kt += 32) {
        // ---- A tile: 128 x 32
#pragma unroll
        for (int it = 0; it < 4; it++) {
            const int r = aRow + it * 32;
            float4 v = *(const float4*)&A[(size_t)(rowBase + r) * K + kt + aC4];
            As[r][aC4 + 0] = tf32r(v.x);
            As[r][aC4 + 1] = tf32r(v.y);
            As[r][aC4 + 2] = tf32r(v.z);
            As[r][aC4 + 3] = tf32r(v.w);
        }
        // ---- B tile: 32 x 128
#pragma unroll
        for (int it = 0; it < 4; it++) {
            const int r = bRow + it * 8;
            float4 v = *(const float4*)&B[(size_t)(kt + r) * N + colBase + bC4];
            Bs[r][bC4 + 0] = tf32r(v.x);
            Bs[r][bC4 + 1] = tf32r(v.y);
            Bs[r][bC4 + 2] = tf32r(v.z);
            Bs[r][bC4 + 3] = tf32r(v.w);
        }
        __syncthreads();

#pragma unroll
        for (int ks = 0; ks < 4; ks++) {
            const int k0 = ks * 8;
            uint32_t af[4][4], bf[4][2];
#pragma unroll
            for (int mi = 0; mi < 4; mi++) {
                const int r0 = wm * 64 + mi * 16 + gid;
                af[mi][0] = As[r0    ][k0 + tig];
                af[mi][1] = As[r0 + 8][k0 + tig];
                af[mi][2] = As[r0    ][k0 + tig + 4];
                af[mi][3] = As[r0 + 8][k0 + tig + 4];
            }
#pragma unroll
            for (int ni = 0; ni < 4; ni++) {
                const int c0 = wn * 32 + ni * 8 + gid;
                bf[ni][0] = Bs[k0 + tig    ][c0];
                bf[ni][1] = Bs[k0 + tig + 4][c0];
            }
#pragma unroll
            for (int mi = 0; mi < 4; mi++)
#pragma unroll
                for (int ni = 0; ni < 4; ni++)
                    mma_tf32(acc[mi][ni], af[mi], bf[ni]);
        }
        __syncthreads();
    }

    // ---- epilogue
#pragma unroll
    for (int mi = 0; mi < 4; mi++) {
#pragma unroll
        for (int ni = 0; ni < 4; ni++) {
            const int row0 = rowBase + wm * 64 + mi * 16 + gid;
            const int col  = colBase + wn * 32 + ni * 8 + tig * 2;
            float b0 = 0.f, b1 = 0.f;
            if (bias) { b0 = bias[col]; b1 = bias[col + 1]; }
            float2 v0, v1;
            v0.x = acc[mi][ni][0] + b0; v0.y = acc[mi][ni][1] + b1;
            v1.x = acc[mi][ni][2] + b0; v1.y = acc[mi][ni][3] + b1;
            *(float2*)&C[(size_t)row0 * N + col] = v0;
            *(float2*)&C[(size_t)(row0 + 8) * N + col] = v1;
        }
    }
}

// ---------------------------------------------------------------------------
// Block-local attention: 1 thread = 1 query row. CTA = 256 q rows of one
// (b, h, chunk) quarter. Key tiles of 32 staged in smem; broadcast LDS.
// Grid = 4*8*4*4 = 512 CTAs.
// ---------------------------------------------------------------------------
__global__ void __launch_bounds__(256)
attn2(const float* __restrict__ qkv, float* __restrict__ o_out)
{
    __shared__ float sk[32][32];
    __shared__ float sv[32][32];

    const int bx = blockIdx.x;
    const int qq = bx & 3;
    const int c  = (bx >> 2) & 3;
    const int h  = (bx >> 4) & 7;
    const int b  = bx >> 7;

    const int tid = threadIdx.x;
    const int n = c * BLKTOK + qq * 256 + tid;

    const float* qp = qkv + ((size_t)(b * NTOK + n)) * QKVD + h * HD;
    float q[32];
#pragma unroll
    for (int d = 0; d < 32; d += 4) {
        float4 v = *(const float4*)(qp + d);
        q[d + 0] = v.x * SCALE_F;
        q[d + 1] = v.y * SCALE_F;
        q[d + 2] = v.z * SCALE_F;
        q[d + 3] = v.w * SCALE_F;
    }

    float m = -1e30f, l = 0.0f;
    float o[32];
#pragma unroll
    for (int d = 0; d < 32; d++) o[d] = 0.0f;

    const int ldRow = tid >> 3;
    const int ldC4  = (tid & 7) * 4;

    for (int kt = 0; kt < 32; kt++) {
        // issue gmem loads early
        const int tok = c * BLKTOK + kt * 32 + ldRow;
        const float* base = qkv + ((size_t)(b * NTOK + tok)) * QKVD + h * HD;
        const float4 kv = *(const float4*)(base + CDIM + ldC4);
        const float4 vv = *(const float4*)(base + 2 * CDIM + ldC4);
        __syncthreads();
        *(float4*)&sk[ldRow][ldC4] = kv;
        *(float4*)&sv[ldRow][ldC4] = vv;
        __syncthreads();

        float s[32];
        float tmax = -1e30f;
#pragma unroll
        for (int j = 0; j < 32; j++) {
            const float4* kr = (const float4*)&sk[j][0];
            float a0 = 0.f, a1 = 0.f, a2 = 0.f, a3 = 0.f;
#pragma unroll
            for (int d4 = 0; d4 < 8; d4++) {
                const float4 k4 = kr[d4];
                a0 = fmaf(q[d4 * 4 + 0], k4.x, a0);
                a1 = fmaf(q[d4 * 4 + 1], k4.y, a1);
                a2 = fmaf(q[d4 * 4 + 2], k4.z, a2);
                a3 = fmaf(q[d4 * 4 + 3], k4.w, a3);
            }
            s[j] = (a0 + a1) + (a2 + a3);
            tmax = fmaxf(tmax, s[j]);
        }

        const float newm = fmaxf(m, tmax);
        const float alpha = __expf(m - newm);
        m = newm;
        l *= alpha;
#pragma unroll
        for (int d = 0; d < 32; d++) o[d] *= alpha;

#pragma unroll
        for (int j = 0; j < 32; j++) {
            const float p = __expf(s[j] - newm);
            l += p;
            const float4* vr = (const float4*)&sv[j][0];
#pragma unroll
            for (int d4 = 0; d4 < 8; d4++) {
                const float4 v4 = vr[d4];
                o[d4 * 4 + 0] = fmaf(p, v4.x, o[d4 * 4 + 0]);
                o[d4 * 4 + 1] = fmaf(p, v4.y, o[d4 * 4 + 1]);
                o[d4 * 4 + 2] = fmaf(p, v4.z, o[d4 * 4 + 2]);
                o[d4 * 4 + 3] = fmaf(p, v4.w, o[d4 * 4 + 3]);
            }
        }
    }

    const float inv = 1.0f / l;
    float* op = o_out + ((size_t)(b * NTOK + n)) * CDIM + h * HD;
#pragma unroll
    for (int d = 0; d < 32; d += 4) {
        float4 v;
        v.x = o[d + 0] * inv;
        v.y = o[d + 1] * inv;
        v.z = o[d + 2] * inv;
        v.w = o[d + 3] * inv;
        *(float4*)(op + d) = v;
    }
}

// ---------------------------------------------------------------------------
// Launch
// ---------------------------------------------------------------------------
extern "C" void kernel_launch(void* const* d_in, const int* in_sizes, int n_in,
                              void* d_out, int out_size)
{
    const float* x    = (const float*)d_in[0];
    const float* Wd   = (const float*)d_in[1];
    const float* Wqkv = (const float*)d_in[2];
    const float* Wup  = (const float*)d_in[3];
    const float* bup  = (const float*)d_in[4];
    float* out = (float*)d_out;

    float *ph, *pqkv, *po;
    cudaGetSymbolAddress((void**)&ph,   g_h);
    cudaGetSymbolAddress((void**)&pqkv, g_qkv);
    cudaGetSymbolAddress((void**)&po,   g_o);

    // GEMM1: h = x @ Wd   [16384,1280]x[1280,256]
    {
        dim3 grid(CDIM / 128, M_TOTAL / 128);
        gemm_mma<<<grid, 256>>>(x, Wd, nullptr, ph, M_TOTAL, CDIM, INCH);
    }
    // GEMM2: qkv = h @ Wqkv   [16384,256]x[256,768]
    {
        dim3 grid(QKVD / 128, M_TOTAL / 128);
        gemm_mma<<<grid, 256>>>(ph, Wqkv, nullptr, pqkv, M_TOTAL, QKVD, CDIM);
    }
    // attention
    attn2<<<BATCH * HEADS * CUT * (BLKTOK / 256), 256>>>(pqkv, po);
    // GEMM3: out = o @ Wup + bup   [16384,256]x[256,1280]
    {
        dim3 grid(INCH / 128, M_TOTAL / 128);
        gemm_mma<<<grid, 256>>>(po, Wup, bup, out, M_TOTAL, INCH, CDIM);
    }
}

// round 4
// speedup vs baseline: 11.9395x; 2.0809x over previous
#include <cuda_runtime.h>
#include <stdint.h>
#include <math.h>

// ---------------------------------------------------------------------------
// Problem constants
// ---------------------------------------------------------------------------
#define BATCH   4
#define NTOK    4096
#define INCH    1280
#define CDIM    256
#define QKVD    768
#define HEADS   8
#define HD      32
#define CUT     4
#define BLKTOK  1024
#define M_TOTAL (BATCH*NTOK)
#define SCALE_F 0.07905694150420949f   // 160^-0.5

// ---------------------------------------------------------------------------
// Scratch
// ---------------------------------------------------------------------------
__device__ float g_h[M_TOTAL * CDIM];
__device__ float g_qkv[M_TOTAL * QKVD];
__device__ float g_o[M_TOTAL * CDIM];

// ---------------------------------------------------------------------------
// tf32 helpers (arch-portable PTX; works on plain sm_103 target)
// ---------------------------------------------------------------------------
__device__ __forceinline__ uint32_t tf32r(float x) {
    uint32_t u;
    asm("cvt.rna.tf32.f32 %0, %1;" : "=r"(u) : "f"(x));
    return u;
}

__device__ __forceinline__ void mma_tf32(float* d, const uint32_t* a, const uint32_t* b) {
    asm volatile(
        "mma.sync.aligned.m16n8k8.row.col.f32.tf32.tf32.f32 "
        "{%0,%1,%2,%3}, {%4,%5,%6,%7}, {%8,%9}, {%0,%1,%2,%3};"
        : "+f"(d[0]), "+f"(d[1]), "+f"(d[2]), "+f"(d[3])
        : "r"(a[0]), "r"(a[1]), "r"(a[2]), "r"(a[3]), "r"(b[0]), "r"(b[1]));
}

// ---------------------------------------------------------------------------
// Tensor-core tf32 GEMM: C[M,N] = A[M,K] @ B[K,N] (+bias)  (proven in R3)
// ---------------------------------------------------------------------------
__global__ void __launch_bounds__(256)
gemm_mma(const float* __restrict__ A, const float* __restrict__ B,
         const float* __restrict__ bias, float* __restrict__ C,
         int M, int N, int K)
{
    __shared__ uint32_t As[128][36];
    __shared__ uint32_t Bs[32][136];

    const int tid  = threadIdx.x;
    const int wid  = tid >> 5;
    const int lane = tid & 31;
    const int gid  = lane >> 2;
    const int tig  = lane & 3;
    const int wm   = wid >> 2;
    const int wn   = wid & 3;
    const int rowBase = blockIdx.y * 128;
    const int colBase = blockIdx.x * 128;

    float acc[4][4][4];
#pragma unroll
    for (int mi = 0; mi < 4; mi++)
#pragma unroll
        for (int ni = 0; ni < 4; ni++)
#pragma unroll
            for (int r = 0; r < 4; r++) acc[mi][ni][r] = 0.0f;

    const int aRow = tid >> 3;
    const int aC4  = (tid & 7) * 4;
    const int bRow = tid >> 5;
    const int bC4  = (tid & 31) * 4;

    for (int kt = 0; kt < K; kt += 32) {
#pragma unroll
        for (int it = 0; it < 4; it++) {
            const int r = aRow + it * 32;
            float4 v = *(const float4*)&A[(size_t)(rowBase + r) * K + kt + aC4];
            As[r][aC4 + 0] = tf32r(v.x);
            As[r][aC4 + 1] = tf32r(v.y);
            As[r][aC4 + 2] = tf32r(v.z);
            As[r][aC4 + 3] = tf32r(v.w);
        }
#pragma unroll
        for (int it = 0; it < 4; it++) {
            const int r = bRow + it * 8;
            float4 v = *(const float4*)&B[(size_t)(kt + r) * N + colBase + bC4];
            Bs[r][bC4 + 0] = tf32r(v.x);
            Bs[r][bC4 + 1] = tf32r(v.y);
            Bs[r][bC4 + 2] = tf32r(v.z);
            Bs[r][bC4 + 3] = tf32r(v.w);
        }
        __syncthreads();

#pragma unroll
        for (int ks = 0; ks < 4; ks++) {
            const int k0 = ks * 8;
            uint32_t af[4][4], bf[4][2];
#pragma unroll
            for (int mi = 0; mi < 4; mi++) {
                const int r0 = wm * 64 + mi * 16 + gid;
                af[mi][0] = As[r0    ][k0 + tig];
                af[mi][1] = As[r0 + 8][k0 + tig];
                af[mi][2] = As[r0    ][k0 + tig + 4];
                af[mi][3] = As[r0 + 8][k0 + tig + 4];
            }
#pragma unroll
            for (int ni = 0; ni < 4; ni++) {
                const int c0 = wn * 32 + ni * 8 + gid;
                bf[ni][0] = Bs[k0 + tig    ][c0];
                bf[ni][1] = Bs[k0 + tig + 4][c0];
            }
#pragma unroll
            for (int mi = 0; mi < 4; mi++)
#pragma unroll
                for (int ni = 0; ni < 4; ni++)
                    mma_tf32(acc[mi][ni], af[mi], bf[ni]);
        }
        __syncthreads();
    }

#pragma unroll
    for (int mi = 0; mi < 4; mi++) {
#pragma unroll
        for (int ni = 0; ni < 4; ni++) {
            const int row0 = rowBase + wm * 64 + mi * 16 + gid;
            const int col  = colBase + wn * 32 + ni * 8 + tig * 2;
            float b0 = 0.f, b1 = 0.f;
            if (bias) { b0 = bias[col]; b1 = bias[col + 1]; }
            float2 v0, v1;
            v0.x = acc[mi][ni][0] + b0; v0.y = acc[mi][ni][1] + b1;
            v1.x = acc[mi][ni][2] + b0; v1.y = acc[mi][ni][3] + b1;
            *(float2*)&C[(size_t)row0 * N + col] = v0;
            *(float2*)&C[(size_t)(row0 + 8) * N + col] = v1;
        }
    }
}

// ---------------------------------------------------------------------------
// Flash-style block-local attention on tf32 tensor cores.
// CTA: 128 q rows of one (b,h,chunk). 8 warps x 16 q rows.
// 16 key tiles of 64. Kt smem [32][72], V smem [64][40], double buffered.
// P repack C-frag -> A-frag via warp shuffles (no smem round trip).
// Grid = 4*8*4*8 = 1024 CTAs.
// ---------------------------------------------------------------------------
__global__ void __launch_bounds__(256)
attn_mma(const float* __restrict__ qkv, float* __restrict__ o_out)
{
    __shared__ uint32_t skT[2][32][72];   // K^T tiles (tf32 bits)
    __shared__ uint32_t svs[2][64][40];   // V tiles (tf32 bits)

    const int bx = blockIdx.x;
    const int qt = bx & 7;
    const int c  = (bx >> 3) & 3;
    const int h  = (bx >> 5) & 7;
    const int b  = bx >> 8;

    const int tid  = threadIdx.x;
    const int wid  = tid >> 5;
    const int lane = tid & 31;
    const int gid  = lane >> 2;
    const int tig  = lane & 3;
    const bool odd = (tig & 1) != 0;
    const int srcA = (gid << 2) | (tig >> 1);
    const int srcB = srcA + 2;

    const size_t rowbase = (size_t)b * NTOK + (size_t)c * BLKTOK;

    // ---- Q A-fragments in registers (pre-scaled, tf32)
    const int q0 = qt * 128 + wid * 16;
    uint32_t qf[4][4];
    {
        const float* qp0 = qkv + (rowbase + q0 + gid) * QKVD + h * HD;
        const float* qp1 = qkv + (rowbase + q0 + gid + 8) * QKVD + h * HD;
#pragma unroll
        for (int ks = 0; ks < 4; ks++) {
            qf[ks][0] = tf32r(qp0[ks * 8 + tig] * SCALE_F);
            qf[ks][1] = tf32r(qp1[ks * 8 + tig] * SCALE_F);
            qf[ks][2] = tf32r(qp0[ks * 8 + tig + 4] * SCALE_F);
            qf[ks][3] = tf32r(qp1[ks * 8 + tig + 4] * SCALE_F);
        }
    }

    // loader indices
    const int keyl = tid >> 2;       // 0..63
    const int d0   = (tid & 3) * 8;  // 0,8,16,24

    // ---- load tile 0
    {
        const float* kp = qkv + (rowbase + keyl) * QKVD + CDIM + h * HD + d0;
        float4 ka = *(const float4*)(kp);
        float4 kb = *(const float4*)(kp + 4);
        float4 va = *(const float4*)(kp + CDIM);
        float4 vb = *(const float4*)(kp + CDIM + 4);
        skT[0][d0 + 0][keyl] = tf32r(ka.x);
        skT[0][d0 + 1][keyl] = tf32r(ka.y);
        skT[0][d0 + 2][keyl] = tf32r(ka.z);
        skT[0][d0 + 3][keyl] = tf32r(ka.w);
        skT[0][d0 + 4][keyl] = tf32r(kb.x);
        skT[0][d0 + 5][keyl] = tf32r(kb.y);
        skT[0][d0 + 6][keyl] = tf32r(kb.z);
        skT[0][d0 + 7][keyl] = tf32r(kb.w);
        uint4 w0 = { tf32r(va.x), tf32r(va.y), tf32r(va.z), tf32r(va.w) };
        uint4 w1 = { tf32r(vb.x), tf32r(vb.y), tf32r(vb.z), tf32r(vb.w) };
        *(uint4*)&svs[0][keyl][d0]     = w0;
        *(uint4*)&svs[0][keyl][d0 + 4] = w1;
    }
    __syncthreads();

    float m0 = -1e30f, m1 = -1e30f, l0 = 0.0f, l1 = 0.0f;
    float o[4][4];
#pragma unroll
    for (int ni = 0; ni < 4; ni++)
#pragma unroll
        for (int r = 0; r < 4; r++) o[ni][r] = 0.0f;

    for (int kt = 0; kt < 16; kt++) {
        const int buf = kt & 1;

        // prefetch next tile into registers (overlaps with compute)
        float4 ka, kb, va, vb;
        if (kt < 15) {
            const float* kp = qkv + (rowbase + (kt + 1) * 64 + keyl) * QKVD + CDIM + h * HD + d0;
            ka = *(const float4*)(kp);
            kb = *(const float4*)(kp + 4);
            va = *(const float4*)(kp + CDIM);
            vb = *(const float4*)(kp + CDIM + 4);
        }

        // ---- S = Q @ K^T  (16 x 64 per warp)
        float s[8][4];
#pragma unroll
        for (int nj = 0; nj < 8; nj++)
#pragma unroll
            for (int r = 0; r < 4; r++) s[nj][r] = 0.0f;

#pragma unroll
        for (int ks = 0; ks < 4; ks++) {
#pragma unroll
            for (int nj = 0; nj < 8; nj++) {
                uint32_t bfr[2];
                bfr[0] = skT[buf][ks * 8 + tig    ][nj * 8 + gid];
                bfr[1] = skT[buf][ks * 8 + tig + 4][nj * 8 + gid];
                mma_tf32(s[nj], qf[ks], bfr);
            }
        }

        // ---- online softmax
        float tmax0 = -1e30f, tmax1 = -1e30f;
#pragma unroll
        for (int nj = 0; nj < 8; nj++) {
            tmax0 = fmaxf(tmax0, fmaxf(s[nj][0], s[nj][1]));
            tmax1 = fmaxf(tmax1, fmaxf(s[nj][2], s[nj][3]));
        }
        tmax0 = fmaxf(tmax0, __shfl_xor_sync(0xffffffffu, tmax0, 1));
        tmax0 = fmaxf(tmax0, __shfl_xor_sync(0xffffffffu, tmax0, 2));
        tmax1 = fmaxf(tmax1, __shfl_xor_sync(0xffffffffu, tmax1, 1));
        tmax1 = fmaxf(tmax1, __shfl_xor_sync(0xffffffffu, tmax1, 2));

        const float m0n = fmaxf(m0, tmax0);
        const float m1n = fmaxf(m1, tmax1);
        const float a0 = __expf(m0 - m0n);
        const float a1 = __expf(m1 - m1n);
        m0 = m0n; m1 = m1n;

        float sum0 = 0.0f, sum1 = 0.0f;
#pragma unroll
        for (int nj = 0; nj < 8; nj++) {
            s[nj][0] = __expf(s[nj][0] - m0);
            s[nj][1] = __expf(s[nj][1] - m0);
            s[nj][2] = __expf(s[nj][2] - m1);
            s[nj][3] = __expf(s[nj][3] - m1);
            sum0 += s[nj][0] + s[nj][1];
            sum1 += s[nj][2] + s[nj][3];
        }
        l0 = l0 * a0 + sum0;
        l1 = l1 * a1 + sum1;
#pragma unroll
        for (int ni = 0; ni < 4; ni++) {
            o[ni][0] *= a0; o[ni][1] *= a0;
            o[ni][2] *= a1; o[ni][3] *= a1;
        }

        // ---- O += P @ V  (repack P via shuffles, 8 k-steps over 64 keys)
#pragma unroll
        for (int kk = 0; kk < 8; kk++) {
            const float v0 = __shfl_sync(0xffffffffu, s[kk][0], srcA);
            const float v1 = __shfl_sync(0xffffffffu, s[kk][1], srcA);
            const float v2 = __shfl_sync(0xffffffffu, s[kk][2], srcA);
            const float v3 = __shfl_sync(0xffffffffu, s[kk][3], srcA);
            const float w0 = __shfl_sync(0xffffffffu, s[kk][0], srcB);
            const float w1 = __shfl_sync(0xffffffffu, s[kk][1], srcB);
            const float w2 = __shfl_sync(0xffffffffu, s[kk][2], srcB);
            const float w3 = __shfl_sync(0xffffffffu, s[kk][3], srcB);
            uint32_t af[4];
            af[0] = tf32r(odd ? v1 : v0);
            af[1] = tf32r(odd ? v3 : v2);
            af[2] = tf32r(odd ? w1 : w0);
            af[3] = tf32r(odd ? w3 : w2);
#pragma unroll
            for (int ni = 0; ni < 4; ni++) {
                uint32_t bfr[2];
                bfr[0] = svs[buf][kk * 8 + tig    ][ni * 8 + gid];
                bfr[1] = svs[buf][kk * 8 + tig + 4][ni * 8 + gid];
                mma_tf32(o[ni], af, bfr);
            }
        }

        // ---- stage next tile into the other buffer
        if (kt < 15) {
            const int nb = buf ^ 1;
            skT[nb][d0 + 0][keyl] = tf32r(ka.x);
            skT[nb][d0 + 1][keyl] = tf32r(ka.y);
            skT[nb][d0 + 2][keyl] = tf32r(ka.z);
            skT[nb][d0 + 3][keyl] = tf32r(ka.w);
            skT[nb][d0 + 4][keyl] = tf32r(kb.x);
            skT[nb][d0 + 5][keyl] = tf32r(kb.y);
            skT[nb][d0 + 6][keyl] = tf32r(kb.z);
            skT[nb][d0 + 7][keyl] = tf32r(kb.w);
            uint4 w0 = { tf32r(va.x), tf32r(va.y), tf32r(va.z), tf32r(va.w) };
            uint4 w1 = { tf32r(vb.x), tf32r(vb.y), tf32r(vb.z), tf32r(vb.w) };
            *(uint4*)&svs[nb][keyl][d0]     = w0;
            *(uint4*)&svs[nb][keyl][d0 + 4] = w1;
        }
        __syncthreads();
    }

    // ---- finalize: quad-reduce l, normalize, write out
    l0 += __shfl_xor_sync(0xffffffffu, l0, 1);
    l0 += __shfl_xor_sync(0xffffffffu, l0, 2);
    l1 += __shfl_xor_sync(0xffffffffu, l1, 1);
    l1 += __shfl_xor_sync(0xffffffffu, l1, 2);
    const float inv0 = 1.0f / l0;
    const float inv1 = 1.0f / l1;

    float* op0 = o_out + (rowbase + q0 + gid) * CDIM + h * HD;
    float* op1 = o_out + (rowbase + q0 + gid + 8) * CDIM + h * HD;
#pragma unroll
    for (int ni = 0; ni < 4; ni++) {
        float2 u0, u1;
        u0.x = o[ni][0] * inv0; u0.y = o[ni][1] * inv0;
        u1.x = o[ni][2] * inv1; u1.y = o[ni][3] * inv1;
        *(float2*)(op0 + ni * 8 + tig * 2) = u0;
        *(float2*)(op1 + ni * 8 + tig * 2) = u1;
    }
}

// ---------------------------------------------------------------------------
// Launch
// ---------------------------------------------------------------------------
extern "C" void kernel_launch(void* const* d_in, const int* in_sizes, int n_in,
                              void* d_out, int out_size)
{
    const float* x    = (const float*)d_in[0];
    const float* Wd   = (const float*)d_in[1];
    const float* Wqkv = (const float*)d_in[2];
    const float* Wup  = (const float*)d_in[3];
    const float* bup  = (const float*)d_in[4];
    float* out = (float*)d_out;

    float *ph, *pqkv, *po;
    cudaGetSymbolAddress((void**)&ph,   g_h);
    cudaGetSymbolAddress((void**)&pqkv, g_qkv);
    cudaGetSymbolAddress((void**)&po,   g_o);

    // GEMM1: h = x @ Wd   [16384,1280]x[1280,256]
    {
        dim3 grid(CDIM / 128, M_TOTAL / 128);
        gemm_mma<<<grid, 256>>>(x, Wd, nullptr, ph, M_TOTAL, CDIM, INCH);
    }
    // GEMM2: qkv = h @ Wqkv   [16384,256]x[256,768]
    {
        dim3 grid(QKVD / 128, M_TOTAL / 128);
        gemm_mma<<<grid, 256>>>(ph, Wqkv, nullptr, pqkv, M_TOTAL, QKVD, CDIM);
    }
    // attention (tensor-core flash)
    attn_mma<<<BATCH * HEADS * CUT * (BLKTOK / 128), 256>>>(pqkv, po);
    // GEMM3: out = o @ Wup + bup   [16384,256]x[256,1280]
    {
        dim3 grid(INCH / 128, M_TOTAL / 128);
        gemm_mma<<<grid, 256>>>(po, Wup, bup, out, M_TOTAL, INCH, CDIM);
    }
}

// round 5
// speedup vs baseline: 12.9565x; 1.0852x over previous
#include <cuda_runtime.h>
#include <stdint.h>
#include <math.h>

// ---------------------------------------------------------------------------
// Problem constants
// ---------------------------------------------------------------------------
#define BATCH   4
#define NTOK    4096
#define INCH    1280
#define CDIM    256
#define QKVD    768
#define HEADS   8
#define HD      32
#define CUT     4
#define BLKTOK  1024
#define M_TOTAL (BATCH*NTOK)
#define SCALE_F 0.07905694150420949f   // 160^-0.5

// ---------------------------------------------------------------------------
// Scratch
// ---------------------------------------------------------------------------
__device__ float g_h[M_TOTAL * CDIM];
__device__ float g_qkv[M_TOTAL * QKVD];
__device__ float g_o[M_TOTAL * CDIM];

// ---------------------------------------------------------------------------
// tf32 helpers (arch-portable PTX; works on plain sm_103 target)
// ---------------------------------------------------------------------------
__device__ __forceinline__ uint32_t tf32r(float x) {
    uint32_t u;
    asm("cvt.rna.tf32.f32 %0, %1;" : "=r"(u) : "f"(x));
    return u;
}

__device__ __forceinline__ void mma_tf32(float* d, const uint32_t* a, const uint32_t* b) {
    asm volatile(
        "mma.sync.aligned.m16n8k8.row.col.f32.tf32.tf32.f32 "
        "{%0,%1,%2,%3}, {%4,%5,%6,%7}, {%8,%9}, {%0,%1,%2,%3};"
        : "+f"(d[0]), "+f"(d[1]), "+f"(d[2]), "+f"(d[3])
        : "r"(a[0]), "r"(a[1]), "r"(a[2]), "r"(a[3]), "r"(b[0]), "r"(b[1]));
}

__device__ __forceinline__ uint32_t smem_u32(const void* p) {
    uint32_t a;
    asm("{ .reg .u64 t; cvta.to.shared.u64 t, %1; cvt.u32.u64 %0, t; }" : "=r"(a) : "l"(p));
    return a;
}

__device__ __forceinline__ void cp_async16(uint32_t dst, const void* src) {
    asm volatile("cp.async.cg.shared.global [%0], [%1], 16;" :: "r"(dst), "l"(src));
}
#define CP_COMMIT() asm volatile("cp.async.commit_group;" ::: "memory")
#define CP_WAIT(n)  asm volatile("cp.async.wait_group %0;" :: "n"(n) : "memory")

// ---------------------------------------------------------------------------
// Tensor-core tf32 GEMM with cp.async double buffering.
// C[M,N] = A[M,K] @ B[K,N] (+bias). CTA tile 128x128, 8 warps, warp 64x32.
// K staged 32. Dynamic smem: As[2][128][36] fp32, Bs[2][32][136] fp32.
// ---------------------------------------------------------------------------
#define AS_STRIDE 36
#define BS_STRIDE 136
#define AS_BUF (128 * AS_STRIDE)            // floats per A buffer
#define BS_BUF (32 * BS_STRIDE)             // floats per B buffer
#define GEMM_SMEM_BYTES ((2 * AS_BUF + 2 * BS_BUF) * 4)   // 71680

__global__ void __launch_bounds__(256)
gemm_mma(const float* __restrict__ A, const float* __restrict__ B,
         const float* __restrict__ bias, float* __restrict__ C,
         int M, int N, int K)
{
    extern __shared__ float smem[];
    float* As = smem;                 // [2][128][36]
    float* Bs = smem + 2 * AS_BUF;    // [2][32][136]

    const int tid  = threadIdx.x;
    const int wid  = tid >> 5;
    const int lane = tid & 31;
    const int gid  = lane >> 2;
    const int tig  = lane & 3;
    const int wm   = wid >> 2;
    const int wn   = wid & 3;
    const int rowBase = blockIdx.y * 128;
    const int colBase = blockIdx.x * 128;

    float acc[4][4][4];
#pragma unroll
    for (int mi = 0; mi < 4; mi++)
#pragma unroll
        for (int ni = 0; ni < 4; ni++)
#pragma unroll
            for (int r = 0; r < 4; r++) acc[mi][ni][r] = 0.0f;

    // loader indices
    const int aRow = tid >> 3;          // 0..31, 4 iters -> 128 rows
    const int aC4  = (tid & 7) * 4;     // 0..28
    const int bRow = tid >> 5;          // 0..7, 4 iters -> 32 rows
    const int bC4  = (tid & 31) * 4;    // 0..124

    const uint32_t asBase = smem_u32(As);
    const uint32_t bsBase = smem_u32(Bs);

    const int nst = K / 32;

    // ---- issue stage 0
    {
#pragma unroll
        for (int it = 0; it < 4; it++) {
            const int r = aRow + it * 32;
            cp_async16(asBase + (r * AS_STRIDE + aC4) * 4,
                       &A[(size_t)(rowBase + r) * K + aC4]);
        }
#pragma unroll
        for (int it = 0; it < 4; it++) {
            const int r = bRow + it * 8;
            cp_async16(bsBase + (r * BS_STRIDE + bC4) * 4,
                       &B[(size_t)r * N + colBase + bC4]);
        }
        CP_COMMIT();
    }

    for (int st = 0; st < nst; st++) {
        const int buf = st & 1;

        // ---- issue stage st+1 into the other buffer
        if (st + 1 < nst) {
            const int nb = buf ^ 1;
            const int kt = (st + 1) * 32;
#pragma unroll
            for (int it = 0; it < 4; it++) {
                const int r = aRow + it * 32;
                cp_async16(asBase + (nb * AS_BUF + r * AS_STRIDE + aC4) * 4,
                           &A[(size_t)(rowBase + r) * K + kt + aC4]);
            }
#pragma unroll
            for (int it = 0; it < 4; it++) {
                const int r = bRow + it * 8;
                cp_async16(bsBase + (nb * BS_BUF + r * BS_STRIDE + bC4) * 4,
                           &B[(size_t)(kt + r) * N + colBase + bC4]);
            }
            CP_COMMIT();
            CP_WAIT(1);
        } else {
            CP_WAIT(0);
        }
        __syncthreads();

        const float* Ab = As + buf * AS_BUF;
        const float* Bb = Bs + buf * BS_BUF;

#pragma unroll
        for (int ks = 0; ks < 4; ks++) {
            const int k0 = ks * 8;
            uint32_t af[4][4], bf[4][2];
#pragma unroll
            for (int mi = 0; mi < 4; mi++) {
                const int r0 = wm * 64 + mi * 16 + gid;
                af[mi][0] = tf32r(Ab[(r0    ) * AS_STRIDE + k0 + tig]);
                af[mi][1] = tf32r(Ab[(r0 + 8) * AS_STRIDE + k0 + tig]);
                af[mi][2] = tf32r(Ab[(r0    ) * AS_STRIDE + k0 + tig + 4]);
                af[mi][3] = tf32r(Ab[(r0 + 8) * AS_STRIDE + k0 + tig + 4]);
            }
#pragma unroll
            for (int ni = 0; ni < 4; ni++) {
                const int c0 = wn * 32 + ni * 8 + gid;
                bf[ni][0] = tf32r(Bb[(k0 + tig    ) * BS_STRIDE + c0]);
                bf[ni][1] = tf32r(Bb[(k0 + tig + 4) * BS_STRIDE + c0]);
            }
#pragma unroll
            for (int mi = 0; mi < 4; mi++)
#pragma unroll
                for (int ni = 0; ni < 4; ni++)
                    mma_tf32(acc[mi][ni], af[mi], bf[ni]);
        }
        __syncthreads();
    }

    // ---- epilogue
#pragma unroll
    for (int mi = 0; mi < 4; mi++) {
#pragma unroll
        for (int ni = 0; ni < 4; ni++) {
            const int row0 = rowBase + wm * 64 + mi * 16 + gid;
            const int col  = colBase + wn * 32 + ni * 8 + tig * 2;
            float b0 = 0.f, b1 = 0.f;
            if (bias) { b0 = bias[col]; b1 = bias[col + 1]; }
            float2 v0, v1;
            v0.x = acc[mi][ni][0] + b0; v0.y = acc[mi][ni][1] + b1;
            v1.x = acc[mi][ni][2] + b0; v1.y = acc[mi][ni][3] + b1;
            *(float2*)&C[(size_t)row0 * N + col] = v0;
            *(float2*)&C[(size_t)(row0 + 8) * N + col] = v1;
        }
    }
}

// ---------------------------------------------------------------------------
// Flash-style block-local attention on tf32 tensor cores (proven in R4).
// ---------------------------------------------------------------------------
__global__ void __launch_bounds__(256)
attn_mma(const float* __restrict__ qkv, float* __restrict__ o_out)
{
    __shared__ uint32_t skT[2][32][72];   // K^T tiles (tf32 bits)
    __shared__ uint32_t svs[2][64][40];   // V tiles (tf32 bits)

    const int bx = blockIdx.x;
    const int qt = bx & 7;
    const int c  = (bx >> 3) & 3;
    const int h  = (bx >> 5) & 7;
    const int b  = bx >> 8;

    const int tid  = threadIdx.x;
    const int wid  = tid >> 5;
    const int lane = tid & 31;
    const int gid  = lane >> 2;
    const int tig  = lane & 3;
    const bool odd = (tig & 1) != 0;
    const int srcA = (gid << 2) | (tig >> 1);
    const int srcB = srcA + 2;

    const size_t rowbase = (size_t)b * NTOK + (size_t)c * BLKTOK;

    const int q0 = qt * 128 + wid * 16;
    uint32_t qf[4][4];
    {
        const float* qp0 = qkv + (rowbase + q0 + gid) * QKVD + h * HD;
        const float* qp1 = qkv + (rowbase + q0 + gid + 8) * QKVD + h * HD;
#pragma unroll
        for (int ks = 0; ks < 4; ks++) {
            qf[ks][0] = tf32r(qp0[ks * 8 + tig] * SCALE_F);
            qf[ks][1] = tf32r(qp1[ks * 8 + tig] * SCALE_F);
            qf[ks][2] = tf32r(qp0[ks * 8 + tig + 4] * SCALE_F);
            qf[ks][3] = tf32r(qp1[ks * 8 + tig + 4] * SCALE_F);
        }
    }

    const int keyl = tid >> 2;
    const int d0   = (tid & 3) * 8;

    {
        const float* kp = qkv + (rowbase + keyl) * QKVD + CDIM + h * HD + d0;
        float4 ka = *(const float4*)(kp);
        float4 kb = *(const float4*)(kp + 4);
        float4 va = *(const float4*)(kp + CDIM);
        float4 vb = *(const float4*)(kp + CDIM + 4);
        skT[0][d0 + 0][keyl] = tf32r(ka.x);
        skT[0][d0 + 1][keyl] = tf32r(ka.y);
        skT[0][d0 + 2][keyl] = tf32r(ka.z);
        skT[0][d0 + 3][keyl] = tf32r(ka.w);
        skT[0][d0 + 4][keyl] = tf32r(kb.x);
        skT[0][d0 + 5][keyl] = tf32r(kb.y);
        skT[0][d0 + 6][keyl] = tf32r(kb.z);
        skT[0][d0 + 7][keyl] = tf32r(kb.w);
        uint4 w0 = { tf32r(va.x), tf32r(va.y), tf32r(va.z), tf32r(va.w) };
        uint4 w1 = { tf32r(vb.x), tf32r(vb.y), tf32r(vb.z), tf32r(vb.w) };
        *(uint4*)&svs[0][keyl][d0]     = w0;
        *(uint4*)&svs[0][keyl][d0 + 4] = w1;
    }
    __syncthreads();

    float m0 = -1e30f, m1 = -1e30f, l0 = 0.0f, l1 = 0.0f;
    float o[4][4];
#pragma unroll
    for (int ni = 0; ni < 4; ni++)
#pragma unroll
        for (int r = 0; r < 4; r++) o[ni][r] = 0.0f;

    for (int kt = 0; kt < 16; kt++) {
        const int buf = kt & 1;

        float4 ka, kb, va, vb;
        if (kt < 15) {
            const float* kp = qkv + (rowbase + (kt + 1) * 64 + keyl) * QKVD + CDIM + h * HD + d0;
            ka = *(const float4*)(kp);
            kb = *(const float4*)(kp + 4);
            va = *(const float4*)(kp + CDIM);
            vb = *(const float4*)(kp + CDIM + 4);
        }

        float s[8][4];
#pragma unroll
        for (int nj = 0; nj < 8; nj++)
#pragma unroll
            for (int r = 0; r < 4; r++) s[nj][r] = 0.0f;

#pragma unroll
        for (int ks = 0; ks < 4; ks++) {
#pragma unroll
            for (int nj = 0; nj < 8; nj++) {
                uint32_t bfr[2];
                bfr[0] = skT[buf][ks * 8 + tig    ][nj * 8 + gid];
                bfr[1] = skT[buf][ks * 8 + tig + 4][nj * 8 + gid];
                mma_tf32(s[nj], qf[ks], bfr);
            }
        }

        float tmax0 = -1e30f, tmax1 = -1e30f;
#pragma unroll
        for (int nj = 0; nj < 8; nj++) {
            tmax0 = fmaxf(tmax0, fmaxf(s[nj][0], s[nj][1]));
            tmax1 = fmaxf(tmax1, fmaxf(s[nj][2], s[nj][3]));
        }
        tmax0 = fmaxf(tmax0, __shfl_xor_sync(0xffffffffu, tmax0, 1));
        tmax0 = fmaxf(tmax0, __shfl_xor_sync(0xffffffffu, tmax0, 2));
        tmax1 = fmaxf(tmax1, __shfl_xor_sync(0xffffffffu, tmax1, 1));
        tmax1 = fmaxf(tmax1, __shfl_xor_sync(0xffffffffu, tmax1, 2));

        const float m0n = fmaxf(m0, tmax0);
        const float m1n = fmaxf(m1, tmax1);
        const float a0 = __expf(m0 - m0n);
        const float a1 = __expf(m1 - m1n);
        m0 = m0n; m1 = m1n;

        float sum0 = 0.0f, sum1 = 0.0f;
#pragma unroll
        for (int nj = 0; nj < 8; nj++) {
            s[nj][0] = __expf(s[nj][0] - m0);
            s[nj][1] = __expf(s[nj][1] - m0);
            s[nj][2] = __expf(s[nj][2] - m1);
            s[nj][3] = __expf(s[nj][3] - m1);
            sum0 += s[nj][0] + s[nj][1];
            sum1 += s[nj][2] + s[nj][3];
        }
        l0 = l0 * a0 + sum0;
        l1 = l1 * a1 + sum1;
#pragma unroll
        for (int ni = 0; ni < 4; ni++) {
            o[ni][0] *= a0; o[ni][1] *= a0;
            o[ni][2] *= a1; o[ni][3] *= a1;
        }

#pragma unroll
        for (int kk = 0; kk < 8; kk++) {
            const float v0 = __shfl_sync(0xffffffffu, s[kk][0], srcA);
            const float v1 = __shfl_sync(0xffffffffu, s[kk][1], srcA);
            const float v2 = __shfl_sync(0xffffffffu, s[kk][2], srcA);
            const float v3 = __shfl_sync(0xffffffffu, s[kk][3], srcA);
            const float w0 = __shfl_sync(0xffffffffu, s[kk][0], srcB);
            const float w1 = __shfl_sync(0xffffffffu, s[kk][1], srcB);
            const float w2 = __shfl_sync(0xffffffffu, s[kk][2], srcB);
            const float w3 = __shfl_sync(0xffffffffu, s[kk][3], srcB);
            uint32_t af[4];
            af[0] = tf32r(odd ? v1 : v0);
            af[1] = tf32r(odd ? v3 : v2);
            af[2] = tf32r(odd ? w1 : w0);
            af[3] = tf32r(odd ? w3 : w2);
#pragma unroll
            for (int ni = 0; ni < 4; ni++) {
                uint32_t bfr[2];
                bfr[0] = svs[buf][kk * 8 + tig    ][ni * 8 + gid];
                bfr[1] = svs[buf][kk * 8 + tig + 4][ni * 8 + gid];
                mma_tf32(o[ni], af, bfr);
            }
        }

        if (kt < 15) {
            const int nb = buf ^ 1;
            skT[nb][d0 + 0][keyl] = tf32r(ka.x);
            skT[nb][d0 + 1][keyl] = tf32r(ka.y);
            skT[nb][d0 + 2][keyl] = tf32r(ka.z);
            skT[nb][d0 + 3][keyl] = tf32r(ka.w);
            skT[nb][d0 + 4][keyl] = tf32r(kb.x);
            skT[nb][d0 + 5][keyl] = tf32r(kb.y);
            skT[nb][d0 + 6][keyl] = tf32r(kb.z);
            skT[nb][d0 + 7][keyl] = tf32r(kb.w);
            uint4 w0 = { tf32r(va.x), tf32r(va.y), tf32r(va.z), tf32r(va.w) };
            uint4 w1 = { tf32r(vb.x), tf32r(vb.y), tf32r(vb.z), tf32r(vb.w) };
            *(uint4*)&svs[nb][keyl][d0]     = w0;
            *(uint4*)&svs[nb][keyl][d0 + 4] = w1;
        }
        __syncthreads();
    }

    l0 += __shfl_xor_sync(0xffffffffu, l0, 1);
    l0 += __shfl_xor_sync(0xffffffffu, l0, 2);
    l1 += __shfl_xor_sync(0xffffffffu, l1, 1);
    l1 += __shfl_xor_sync(0xffffffffu, l1, 2);
    const float inv0 = 1.0f / l0;
    const float inv1 = 1.0f / l1;

    float* op0 = o_out + (rowbase + q0 + gid) * CDIM + h * HD;
    float* op1 = o_out + (rowbase + q0 + gid + 8) * CDIM + h * HD;
#pragma unroll
    for (int ni = 0; ni < 4; ni++) {
        float2 u0, u1;
        u0.x = o[ni][0] * inv0; u0.y = o[ni][1] * inv0;
        u1.x = o[ni][2] * inv1; u1.y = o[ni][3] * inv1;
        *(float2*)(op0 + ni * 8 + tig * 2) = u0;
        *(float2*)(op1 + ni * 8 + tig * 2) = u1;
    }
}

// ---------------------------------------------------------------------------
// Launch
// ---------------------------------------------------------------------------
extern "C" void kernel_launch(void* const* d_in, const int* in_sizes, int n_in,
                              void* d_out, int out_size)
{
    const float* x    = (const float*)d_in[0];
    const float* Wd   = (const float*)d_in[1];
    const float* Wqkv = (const float*)d_in[2];
    const float* Wup  = (const float*)d_in[3];
    const float* bup  = (const float*)d_in[4];
    float* out = (float*)d_out;

    float *ph, *pqkv, *po;
    cudaGetSymbolAddress((void**)&ph,   g_h);
    cudaGetSymbolAddress((void**)&pqkv, g_qkv);
    cudaGetSymbolAddress((void**)&po,   g_o);

    cudaFuncSetAttribute(gemm_mma, cudaFuncAttributeMaxDynamicSharedMemorySize,
                         GEMM_SMEM_BYTES);

    // GEMM1: h = x @ Wd   [16384,1280]x[1280,256]
    {
        dim3 grid(CDIM / 128, M_TOTAL / 128);
        gemm_mma<<<grid, 256, GEMM_SMEM_BYTES>>>(x, Wd, nullptr, ph, M_TOTAL, CDIM, INCH);
    }
    // GEMM2: qkv = h @ Wqkv   [16384,256]x[256,768]
    {
        dim3 grid(QKVD / 128, M_TOTAL / 128);
        gemm_mma<<<grid, 256, GEMM_SMEM_BYTES>>>(ph, Wqkv, nullptr, pqkv, M_TOTAL, QKVD, CDIM);
    }
    // attention (tensor-core flash)
    attn_mma<<<BATCH * HEADS * CUT * (BLKTOK / 128), 256>>>(pqkv, po);
    // GEMM3: out = o @ Wup + bup   [16384,256]x[256,1280]
    {
        dim3 grid(INCH / 128, M_TOTAL / 128);
        gemm_mma<<<grid, 256, GEMM_SMEM_BYTES>>>(po, Wup, bup, out, M_TOTAL, INCH, CDIM);
    }
}

// round 6
// speedup vs baseline: 13.2258x; 1.0208x over previous
#include <cuda_runtime.h>
#include <stdint.h>
#include <math.h>

// ---------------------------------------------------------------------------
// Problem constants
// ---------------------------------------------------------------------------
#define BATCH   4
#define NTOK    4096
#define INCH    1280
#define CDIM    256
#define QKVD    768
#define HEADS   8
#define HD      32
#define CUT     4
#define BLKTOK  1024
#define M_TOTAL (BATCH*NTOK)
#define SCALE_F 0.07905694150420949f   // 160^-0.5

// ---------------------------------------------------------------------------
// Scratch
// ---------------------------------------------------------------------------
__device__ float g_h[M_TOTAL * CDIM];
__device__ float g_qkv[M_TOTAL * QKVD];
__device__ float g_o[M_TOTAL * CDIM];
// K-major, tf32-pre-rounded weights
__device__ float g_wdT[CDIM * INCH];     // [256][1280]
__device__ float g_wqkvT[QKVD * CDIM];   // [768][256]
__device__ float g_wupT[INCH * CDIM];    // [1280][256]

// ---------------------------------------------------------------------------
// helpers
// ---------------------------------------------------------------------------
__device__ __forceinline__ uint32_t tf32r(float x) {
    uint32_t u;
    asm("cvt.rna.tf32.f32 %0, %1;" : "=r"(u) : "f"(x));
    return u;
}
__device__ __forceinline__ float tf32f(float x) { return __uint_as_float(tf32r(x)); }

__device__ __forceinline__ void mma_tf32(float* d, const uint32_t* a, const uint32_t* b) {
    asm volatile(
        "mma.sync.aligned.m16n8k8.row.col.f32.tf32.tf32.f32 "
        "{%0,%1,%2,%3}, {%4,%5,%6,%7}, {%8,%9}, {%0,%1,%2,%3};"
        : "+f"(d[0]), "+f"(d[1]), "+f"(d[2]), "+f"(d[3])
        : "r"(a[0]), "r"(a[1]), "r"(a[2]), "r"(a[3]), "r"(b[0]), "r"(b[1]));
}

__device__ __forceinline__ uint32_t smem_u32(const void* p) {
    uint32_t a;
    asm("{ .reg .u64 t; cvta.to.shared.u64 t, %1; cvt.u32.u64 %0, t; }" : "=r"(a) : "l"(p));
    return a;
}
__device__ __forceinline__ void cp_async16(uint32_t dst, const void* src) {
    asm volatile("cp.async.cg.shared.global [%0], [%1], 16;" :: "r"(dst), "l"(src));
}
#define CP_COMMIT() asm volatile("cp.async.commit_group;" ::: "memory")
#define CP_WAIT(n)  asm volatile("cp.async.wait_group %0;" :: "n"(n) : "memory")

// ---------------------------------------------------------------------------
// Weight transpose + tf32 pre-round: WT[n][k] = tf32(W[k][n])
// ---------------------------------------------------------------------------
__global__ void transpose_tf32(const float* __restrict__ W, float* __restrict__ WT,
                               int K, int N)
{
    __shared__ float t[32][33];
    const int kb = blockIdx.x * 32, nb = blockIdx.y * 32;
    const int tx = threadIdx.x, ty = threadIdx.y;   // 32 x 8
#pragma unroll
    for (int i = 0; i < 4; i++)
        t[ty + 8 * i][tx] = W[(size_t)(kb + ty + 8 * i) * N + nb + tx];
    __syncthreads();
#pragma unroll
    for (int i = 0; i < 4; i++)
        WT[(size_t)(nb + ty + 8 * i) * K + kb + tx] = tf32f(t[tx][ty + 8 * i]);
}

// ---------------------------------------------------------------------------
// Tensor-core tf32 GEMM, k-permuted vectorized fragments.
// C[M,N] = A[M,K] @ BT[N,K]^T (+bias). CTA 128x128, 4 warps (2x2), warp 64x64.
// Smem: As[2][128][48], Bs[2][128][48] fp32 (row stride 48 -> granule stride 12,
// conflict-free LDS.128). cp.async double buffered. K staged 32.
// k-permutation: mma step (s0,s1): lane tig supplies k = 4*tig+s0 / 4*tig+s1
// (identically on A and B), so fragments are contiguous float4s.
// ---------------------------------------------------------------------------
#define GSTRIDE 48
#define GBUF (128 * GSTRIDE)
#define GEMM_SMEM_BYTES (4 * GBUF * 4)   // 98304

template<bool CVT_A, bool ROUND_OUT>
__global__ void __launch_bounds__(128, 2)
gemm_mma(const float* __restrict__ A, const float* __restrict__ BT,
         const float* __restrict__ bias, float* __restrict__ C,
         int M, int N, int K)
{
    extern __shared__ float smem[];
    float* As = smem;                // [2][128][48]
    float* Bs = smem + 2 * GBUF;     // [2][128][48]

    const int tid  = threadIdx.x;
    const int wid  = tid >> 5;
    const int lane = tid & 31;
    const int gid  = lane >> 2;
    const int tig  = lane & 3;
    const int wm   = wid >> 1;       // 0..1
    const int wn   = wid & 1;        // 0..1
    const int rowBase = blockIdx.y * 128;
    const int colBase = blockIdx.x * 128;

    float acc[4][8][4];
#pragma unroll
    for (int mi = 0; mi < 4; mi++)
#pragma unroll
        for (int ni = 0; ni < 8; ni++)
#pragma unroll
            for (int r = 0; r < 4; r++) acc[mi][ni][r] = 0.0f;

    // fill indices: 128 threads, 8 iters -> 128 rows x 8 granules
    const int fr = tid >> 3;         // 0..15
    const int fc = (tid & 7) * 4;    // 0..28 (granule*4 floats)

    const uint32_t asBase = smem_u32(As);
    const uint32_t bsBase = smem_u32(Bs);
    const int nst = K / 32;

    // ---- stage 0
#pragma unroll
    for (int it = 0; it < 8; it++) {
        const int r = fr + 16 * it;
        cp_async16(asBase + (r * GSTRIDE + fc) * 4, &A[(size_t)(rowBase + r) * K + fc]);
        cp_async16(bsBase + (r * GSTRIDE + fc) * 4, &BT[(size_t)(colBase + r) * K + fc]);
    }
    CP_COMMIT();

    for (int st = 0; st < nst; st++) {
        const int buf = st & 1;
        if (st + 1 < nst) {
            const int nb = buf ^ 1;
            const int kt = (st + 1) * 32;
#pragma unroll
            for (int it = 0; it < 8; it++) {
                const int r = fr + 16 * it;
                cp_async16(asBase + (nb * GBUF + r * GSTRIDE + fc) * 4,
                           &A[(size_t)(rowBase + r) * K + kt + fc]);
                cp_async16(bsBase + (nb * GBUF + r * GSTRIDE + fc) * 4,
                           &BT[(size_t)(colBase + r) * K + kt + fc]);
            }
            CP_COMMIT();
            CP_WAIT(1);
        } else {
            CP_WAIT(0);
        }
        __syncthreads();

        const float4* A4 = (const float4*)(As + buf * GBUF);
        const float4* B4 = (const float4*)(Bs + buf * GBUF);

#pragma unroll
        for (int h = 0; h < 2; h++) {
            const int g = tig + 4 * h;
            float4 a0[4], a1[4];
#pragma unroll
            for (int mi = 0; mi < 4; mi++) {
                const int r0 = wm * 64 + mi * 16 + gid;
                a0[mi] = A4[r0 * 12 + g];
                a1[mi] = A4[(r0 + 8) * 12 + g];
                if (CVT_A) {
                    a0[mi].x = tf32f(a0[mi].x); a0[mi].y = tf32f(a0[mi].y);
                    a0[mi].z = tf32f(a0[mi].z); a0[mi].w = tf32f(a0[mi].w);
                    a1[mi].x = tf32f(a1[mi].x); a1[mi].y = tf32f(a1[mi].y);
                    a1[mi].z = tf32f(a1[mi].z); a1[mi].w = tf32f(a1[mi].w);
                }
            }
            float4 bv[8];
#pragma unroll
            for (int ni = 0; ni < 8; ni++) {
                const int c0 = wn * 64 + ni * 8 + gid;
                bv[ni] = B4[c0 * 12 + g];
            }
#pragma unroll
            for (int mi = 0; mi < 4; mi++) {
#pragma unroll
                for (int ni = 0; ni < 8; ni++) {
                    uint32_t af[4], bf[2];
                    af[0] = __float_as_uint(a0[mi].x);
                    af[1] = __float_as_uint(a1[mi].x);
                    af[2] = __float_as_uint(a0[mi].y);
                    af[3] = __float_as_uint(a1[mi].y);
                    bf[0] = __float_as_uint(bv[ni].x);
                    bf[1] = __float_as_uint(bv[ni].y);
                    mma_tf32(acc[mi][ni], af, bf);
                    af[0] = __float_as_uint(a0[mi].z);
                    af[1] = __float_as_uint(a1[mi].z);
                    af[2] = __float_as_uint(a0[mi].w);
                    af[3] = __float_as_uint(a1[mi].w);
                    bf[0] = __float_as_uint(bv[ni].z);
                    bf[1] = __float_as_uint(bv[ni].w);
                    mma_tf32(acc[mi][ni], af, bf);
                }
            }
        }
        __syncthreads();
    }

    // ---- epilogue
#pragma unroll
    for (int mi = 0; mi < 4; mi++) {
#pragma unroll
        for (int ni = 0; ni < 8; ni++) {
            const int row0 = rowBase + wm * 64 + mi * 16 + gid;
            const int col  = colBase + wn * 64 + ni * 8 + tig * 2;
            float b0 = 0.f, b1 = 0.f;
            if (bias) { b0 = bias[col]; b1 = bias[col + 1]; }
            float2 v0, v1;
            v0.x = acc[mi][ni][0] + b0; v0.y = acc[mi][ni][1] + b1;
            v1.x = acc[mi][ni][2] + b0; v1.y = acc[mi][ni][3] + b1;
            if (ROUND_OUT) {
                v0.x = tf32f(v0.x); v0.y = tf32f(v0.y);
                v1.x = tf32f(v1.x); v1.y = tf32f(v1.y);
            }
            *(float2*)&C[(size_t)row0 * N + col] = v0;
            *(float2*)&C[(size_t)(row0 + 8) * N + col] = v1;
        }
    }
}

// ---------------------------------------------------------------------------
// Flash-style block-local attention on tf32 tensor cores (proven in R4).
// qkv arrives tf32-pre-rounded -> k/v staged raw; o written tf32-rounded.
// ---------------------------------------------------------------------------
__global__ void __launch_bounds__(256)
attn_mma(const float* __restrict__ qkv, float* __restrict__ o_out)
{
    __shared__ uint32_t skT[2][32][72];   // K^T tiles (tf32 bits)
    __shared__ uint32_t svs[2][64][40];   // V tiles (tf32 bits)

    const int bx = blockIdx.x;
    const int qt = bx & 7;
    const int c  = (bx >> 3) & 3;
    const int h  = (bx >> 5) & 7;
    const int b  = bx >> 8;

    const int tid  = threadIdx.x;
    const int wid  = tid >> 5;
    const int lane = tid & 31;
    const int gid  = lane >> 2;
    const int tig  = lane & 3;
    const bool odd = (tig & 1) != 0;
    const int srcA = (gid << 2) | (tig >> 1);
    const int srcB = srcA + 2;

    const size_t rowbase = (size_t)b * NTOK + (size_t)c * BLKTOK;

    const int q0 = qt * 128 + wid * 16;
    uint32_t qf[4][4];
    {
        const float* qp0 = qkv + (rowbase + q0 + gid) * QKVD + h * HD;
        const float* qp1 = qkv + (rowbase + q0 + gid + 8) * QKVD + h * HD;
#pragma unroll
        for (int ks = 0; ks < 4; ks++) {
            qf[ks][0] = tf32r(qp0[ks * 8 + tig] * SCALE_F);
            qf[ks][1] = tf32r(qp1[ks * 8 + tig] * SCALE_F);
            qf[ks][2] = tf32r(qp0[ks * 8 + tig + 4] * SCALE_F);
            qf[ks][3] = tf32r(qp1[ks * 8 + tig + 4] * SCALE_F);
        }
    }

    const int keyl = tid >> 2;
    const int d0   = (tid & 3) * 8;

    {
        const uint32_t* kp = (const uint32_t*)(qkv + (rowbase + keyl) * QKVD + CDIM + h * HD + d0);
        uint4 ka = *(const uint4*)(kp);
        uint4 kb = *(const uint4*)(kp + 4);
        uint4 va = *(const uint4*)(kp + CDIM);
        uint4 vb = *(const uint4*)(kp + CDIM + 4);
        skT[0][d0 + 0][keyl] = ka.x; skT[0][d0 + 1][keyl] = ka.y;
        skT[0][d0 + 2][keyl] = ka.z; skT[0][d0 + 3][keyl] = ka.w;
        skT[0][d0 + 4][keyl] = kb.x; skT[0][d0 + 5][keyl] = kb.y;
        skT[0][d0 + 6][keyl] = kb.z; skT[0][d0 + 7][keyl] = kb.w;
        *(uint4*)&svs[0][keyl][d0]     = va;
        *(uint4*)&svs[0][keyl][d0 + 4] = vb;
    }
    __syncthreads();

    float m0 = -1e30f, m1 = -1e30f, l0 = 0.0f, l1 = 0.0f;
    float o[4][4];
#pragma unroll
    for (int ni = 0; ni < 4; ni++)
#pragma unroll
        for (int r = 0; r < 4; r++) o[ni][r] = 0.0f;

    for (int kt = 0; kt < 16; kt++) {
        const int buf = kt & 1;

        uint4 ka, kb, va, vb;
        if (kt < 15) {
            const uint32_t* kp = (const uint32_t*)(qkv + (rowbase + (kt + 1) * 64 + keyl) * QKVD + CDIM + h * HD + d0);
            ka = *(const uint4*)(kp);
            kb = *(const uint4*)(kp + 4);
            va = *(const uint4*)(kp + CDIM);
            vb = *(const uint4*)(kp + CDIM + 4);
        }

        float s[8][4];
#pragma unroll
        for (int nj = 0; nj < 8; nj++)
#pragma unroll
            for (int r = 0; r < 4; r++) s[nj][r] = 0.0f;

#pragma unroll
        for (int ks = 0; ks < 4; ks++) {
#pragma unroll
            for (int nj = 0; nj < 8; nj++) {
                uint32_t bfr[2];
                bfr[0] = skT[buf][ks * 8 + tig    ][nj * 8 + gid];
                bfr[1] = skT[buf][ks * 8 + tig + 4][nj * 8 + gid];
                mma_tf32(s[nj], qf[ks], bfr);
            }
        }

        float tmax0 = -1e30f, tmax1 = -1e30f;
#pragma unroll
        for (int nj = 0; nj < 8; nj++) {
            tmax0 = fmaxf(tmax0, fmaxf(s[nj][0], s[nj][1]));
            tmax1 = fmaxf(tmax1, fmaxf(s[nj][2], s[nj][3]));
        }
        tmax0 = fmaxf(tmax0, __shfl_xor_sync(0xffffffffu, tmax0, 1));
        tmax0 = fmaxf(tmax0, __shfl_xor_sync(0xffffffffu, tmax0, 2));
        tmax1 = fmaxf(tmax1, __shfl_xor_sync(0xffffffffu, tmax1, 1));
        tmax1 = fmaxf(tmax1, __shfl_xor_sync(0xffffffffu, tmax1, 2));

        const float m0n = fmaxf(m0, tmax0);
        const float m1n = fmaxf(m1, tmax1);
        const float a0 = __expf(m0 - m0n);
        const float a1 = __expf(m1 - m1n);
        m0 = m0n; m1 = m1n;

        float sum0 = 0.0f, sum1 = 0.0f;
#pragma unroll
        for (int nj = 0; nj < 8; nj++) {
            s[nj][0] = __expf(s[nj][0] - m0);
            s[nj][1] = __expf(s[nj][1] - m0);
            s[nj][2] = __expf(s[nj][2] - m1);
            s[nj][3] = __expf(s[nj][3] - m1);
            sum0 += s[nj][0] + s[nj][1];
            sum1 += s[nj][2] + s[nj][3];
        }
        l0 = l0 * a0 + sum0;
        l1 = l1 * a1 + sum1;
#pragma unroll
        for (int ni = 0; ni < 4; ni++) {
            o[ni][0] *= a0; o[ni][1] *= a0;
            o[ni][2] *= a1; o[ni][3] *= a1;
        }

#pragma unroll
        for (int kk = 0; kk < 8; kk++) {
            const float v0 = __shfl_sync(0xffffffffu, s[kk][0], srcA);
            const float v1 = __shfl_sync(0xffffffffu, s[kk][1], srcA);
            const float v2 = __shfl_sync(0xffffffffu, s[kk][2], srcA);
            const float v3 = __shfl_sync(0xffffffffu, s[kk][3], srcA);
            const float w0 = __shfl_sync(0xffffffffu, s[kk][0], srcB);
            const float w1 = __shfl_sync(0xffffffffu, s[kk][1], srcB);
            const float w2 = __shfl_sync(0xffffffffu, s[kk][2], srcB);
            const float w3 = __shfl_sync(0xffffffffu, s[kk][3], srcB);
            uint32_t af[4];
            af[0] = tf32r(odd ? v1 : v0);
            af[1] = tf32r(odd ? v3 : v2);
            af[2] = tf32r(odd ? w1 : w0);
            af[3] = tf32r(odd ? w3 : w2);
#pragma unroll
            for (int ni = 0; ni < 4; ni++) {
                uint32_t bfr[2];
                bfr[0] = svs[buf][kk * 8 + tig    ][ni * 8 + gid];
                bfr[1] = svs[buf][kk * 8 + tig + 4][ni * 8 + gid];
                mma_tf32(o[ni], af, bfr);
            }
        }

        if (kt < 15) {
            const int nb = buf ^ 1;
            skT[nb][d0 + 0][keyl] = ka.x; skT[nb][d0 + 1][keyl] = ka.y;
            skT[nb][d0 + 2][keyl] = ka.z; skT[nb][d0 + 3][keyl] = ka.w;
            skT[nb][d0 + 4][keyl] = kb.x; skT[nb][d0 + 5][keyl] = kb.y;
            skT[nb][d0 + 6][keyl] = kb.z; skT[nb][d0 + 7][keyl] = kb.w;
            *(uint4*)&svs[nb][keyl][d0]     = va;
            *(uint4*)&svs[nb][keyl][d0 + 4] = vb;
        }
        __syncthreads();
    }

    l0 += __shfl_xor_sync(0xffffffffu, l0, 1);
    l0 += __shfl_xor_sync(0xffffffffu, l0, 2);
    l1 += __shfl_xor_sync(0xffffffffu, l1, 1);
    l1 += __shfl_xor_sync(0xffffffffu, l1, 2);
    const float inv0 = 1.0f / l0;
    const float inv1 = 1.0f / l1;

    float* op0 = o_out + (rowbase + q0 + gid) * CDIM + h * HD;
    float* op1 = o_out + (rowbase + q0 + gid + 8) * CDIM + h * HD;
#pragma unroll
    for (int ni = 0; ni < 4; ni++) {
        float2 u0, u1;
        u0.x = tf32f(o[ni][0] * inv0); u0.y = tf32f(o[ni][1] * inv0);
        u1.x = tf32f(o[ni][2] * inv1); u1.y = tf32f(o[ni][3] * inv1);
        *(float2*)(op0 + ni * 8 + tig * 2) = u0;
        *(float2*)(op1 + ni * 8 + tig * 2) = u1;
    }
}

// ---------------------------------------------------------------------------
// Launch
// ---------------------------------------------------------------------------
extern "C" void kernel_launch(void* const* d_in, const int* in_sizes, int n_in,
                              void* d_out, int out_size)
{
    const float* x    = (const float*)d_in[0];
    const float* Wd   = (const float*)d_in[1];
    const float* Wqkv = (const float*)d_in[2];
    const float* Wup  = (const float*)d_in[3];
    const float* bup  = (const float*)d_in[4];
    float* out = (float*)d_out;

    float *ph, *pqkv, *po, *pwdT, *pwqkvT, *pwupT;
    cudaGetSymbolAddress((void**)&ph,     g_h);
    cudaGetSymbolAddress((void**)&pqkv,   g_qkv);
    cudaGetSymbolAddress((void**)&po,     g_o);
    cudaGetSymbolAddress((void**)&pwdT,   g_wdT);
    cudaGetSymbolAddress((void**)&pwqkvT, g_wqkvT);
    cudaGetSymbolAddress((void**)&pwupT,  g_wupT);

    cudaFuncSetAttribute(gemm_mma<true, true>,
                         cudaFuncAttributeMaxDynamicSharedMemorySize, GEMM_SMEM_BYTES);
    cudaFuncSetAttribute(gemm_mma<false, true>,
                         cudaFuncAttributeMaxDynamicSharedMemorySize, GEMM_SMEM_BYTES);
    cudaFuncSetAttribute(gemm_mma<false, false>,
                         cudaFuncAttributeMaxDynamicSharedMemorySize, GEMM_SMEM_BYTES);

    // weight transposes (K-major, tf32-rounded)
    {
        dim3 blk(32, 8);
        transpose_tf32<<<dim3(INCH / 32, CDIM / 32), blk>>>(Wd,   pwdT,   INCH, CDIM);
        transpose_tf32<<<dim3(CDIM / 32, QKVD / 32), blk>>>(Wqkv, pwqkvT, CDIM, QKVD);
        transpose_tf32<<<dim3(CDIM / 32, INCH / 32), blk>>>(Wup,  pwupT,  CDIM, INCH);
    }

    // GEMM1: h = x @ Wd   (A raw -> cvt at consume; h stored tf32-rounded)
    {
        dim3 grid(CDIM / 128, M_TOTAL / 128);
        gemm_mma<true, true><<<grid, 128, GEMM_SMEM_BYTES>>>(x, pwdT, nullptr, ph,
                                                             M_TOTAL, CDIM, INCH);
    }
    // GEMM2: qkv = h @ Wqkv   (pre-rounded A; qkv stored tf32-rounded)
    {
        dim3 grid(QKVD / 128, M_TOTAL / 128);
        gemm_mma<false, true><<<grid, 128, GEMM_SMEM_BYTES>>>(ph, pwqkvT, nullptr, pqkv,
                                                              M_TOTAL, QKVD, CDIM);
    }
    // attention (tensor-core flash); writes o tf32-rounded
    attn_mma<<<BATCH * HEADS * CUT * (BLKTOK / 128), 256>>>(pqkv, po);
    // GEMM3: out = o @ Wup + bup   (pre-rounded A; fp32 out)
    {
        dim3 grid(INCH / 128, M_TOTAL / 128);
        gemm_mma<false, false><<<grid, 128, GEMM_SMEM_BYTES>>>(po, pwupT, bup, out,
                                                               M_TOTAL, INCH, CDIM);
    }
}

// round 7
// speedup vs baseline: 19.1908x; 1.4510x over previous
#include <cuda_runtime.h>
#include <cuda_fp16.h>
#include <stdint.h>
#include <math.h>

// ---------------------------------------------------------------------------
// Problem constants
// ---------------------------------------------------------------------------
#define BATCH   4
#define NTOK    4096
#define INCH    1280
#define CDIM    256
#define QKVD    768
#define HEADS   8
#define HD      32
#define CUT     4
#define BLKTOK  1024
#define M_TOTAL (BATCH*NTOK)
#define SCALE_F 0.07905694150420949f   // 160^-0.5
#define C2LOG   (SCALE_F * 1.4426950408889634f)   // SCALE * log2(e)

// ---------------------------------------------------------------------------
// Scratch (fp16 operand world, fp32 final out)
// ---------------------------------------------------------------------------
__device__ __half g_x16[M_TOTAL * INCH];
__device__ __half g_h16[M_TOTAL * CDIM];
__device__ __half g_qkv16[M_TOTAL * QKVD];
__device__ __half g_o16[M_TOTAL * CDIM];
__device__ __half g_wdT[CDIM * INCH];     // K-major [256][1280]
__device__ __half g_wqkvT[QKVD * CDIM];   // [768][256]
__device__ __half g_wupT[INCH * CDIM];    // [1280][256]

// ---------------------------------------------------------------------------
// helpers
// ---------------------------------------------------------------------------
__device__ __forceinline__ void mma_f16(float* d, const uint32_t* a, const uint32_t* b) {
    asm volatile(
        "mma.sync.aligned.m16n8k16.row.col.f32.f16.f16.f32 "
        "{%0,%1,%2,%3}, {%4,%5,%6,%7}, {%8,%9}, {%0,%1,%2,%3};"
        : "+f"(d[0]), "+f"(d[1]), "+f"(d[2]), "+f"(d[3])
        : "r"(a[0]), "r"(a[1]), "r"(a[2]), "r"(a[3]), "r"(b[0]), "r"(b[1]));
}
__device__ __forceinline__ uint32_t smem_u32(const void* p) {
    uint32_t a;
    asm("{ .reg .u64 t; cvta.to.shared.u64 t, %1; cvt.u32.u64 %0, t; }" : "=r"(a) : "l"(p));
    return a;
}
__device__ __forceinline__ void cp_async16(uint32_t dst, const void* src) {
    asm volatile("cp.async.cg.shared.global [%0], [%1], 16;" :: "r"(dst), "l"(src));
}
#define CP_COMMIT() asm volatile("cp.async.commit_group;" ::: "memory")
#define CP_WAIT(n)  asm volatile("cp.async.wait_group %0;" :: "n"(n) : "memory")

__device__ __forceinline__ uint32_t packh2(float lo, float hi) {
    __half2 h = __floats2half2_rn(lo, hi);
    return *(uint32_t*)&h;
}

// ---------------------------------------------------------------------------
// fp32 -> fp16 conversion (vector 8)
// ---------------------------------------------------------------------------
__global__ void cvt_f32_f16(const float* __restrict__ s, __half* __restrict__ d, int n)
{
    const int i = (blockIdx.x * 256 + threadIdx.x) * 8;
    if (i < n) {
        float4 v0 = *(const float4*)(s + i);
        float4 v1 = *(const float4*)(s + i + 4);
        uint4 o;
        o.x = packh2(v0.x, v0.y);
        o.y = packh2(v0.z, v0.w);
        o.z = packh2(v1.x, v1.y);
        o.w = packh2(v1.z, v1.w);
        *(uint4*)(d + i) = o;
    }
}

// ---------------------------------------------------------------------------
// Weight transpose fp32 -> fp16 K-major: WT[n][k] = (half)W[k][n]
// ---------------------------------------------------------------------------
__global__ void transpose_f16(const float* __restrict__ W, __half* __restrict__ WT,
                              int K, int N)
{
    __shared__ float t[32][33];
    const int kb = blockIdx.x * 32, nb = blockIdx.y * 32;
    const int tx = threadIdx.x, ty = threadIdx.y;   // 32 x 8
#pragma unroll
    for (int i = 0; i < 4; i++)
        t[ty + 8 * i][tx] = W[(size_t)(kb + ty + 8 * i) * N + nb + tx];
    __syncthreads();
#pragma unroll
    for (int i = 0; i < 4; i++)
        WT[(size_t)(nb + ty + 8 * i) * K + kb + tx] = __float2half_rn(t[tx][ty + 8 * i]);
}

// ---------------------------------------------------------------------------
// fp16 tensor-core GEMM: C = A[M,K] @ BT[N,K]^T (+bias).
// CTA 128x128, 4 warps (2x2), warp 64x64. K staged 32 halves (16 b32).
// Smem tiles [128][16 b32], no pad (granule stride 4 -> conflict-free uint4).
// cp.async double buffered. b32-pair k-permutation: thread tig's uint4 covers
// b32 {4tig..4tig+3}; group0 = (.x,.y), group1 = (.z,.w), same map on A and B.
// ---------------------------------------------------------------------------
#define GB32  16                      // b32 per row per stage
#define GBUFU (128 * GB32)            // b32 per buffer
#define GEMM_SMEM_BYTES (4 * GBUFU * 4)   // 32768

template<bool OUT_HALF>
__global__ void __launch_bounds__(128, 2)
gemm_f16(const __half* __restrict__ A, const __half* __restrict__ BT,
         const float* __restrict__ bias, void* __restrict__ Cv,
         int M, int N, int K)
{
    extern __shared__ uint32_t smem[];
    uint32_t* As = smem;               // [2][128][16]
    uint32_t* Bs = smem + 2 * GBUFU;   // [2][128][16]

    const int tid  = threadIdx.x;
    const int wid  = tid >> 5;
    const int lane = tid & 31;
    const int gid  = lane >> 2;
    const int tig  = lane & 3;
    const int wm   = wid >> 1;
    const int wn   = wid & 1;
    const int rowBase = blockIdx.y * 128;
    const int colBase = blockIdx.x * 128;

    float acc[4][8][4];
#pragma unroll
    for (int mi = 0; mi < 4; mi++)
#pragma unroll
        for (int ni = 0; ni < 8; ni++)
#pragma unroll
            for (int r = 0; r < 4; r++) acc[mi][ni][r] = 0.0f;

    // fill: 128 rows x 4 granules (16B) per operand = 512 chunks / 128 thr = 4
    const int fr = tid >> 2;          // 0..31, 4 iters -> 128 rows
    const int fg = tid & 3;           // granule 0..3 (8 halves)

    const uint32_t asBase = smem_u32(As);
    const uint32_t bsBase = smem_u32(Bs);
    const int nst = K / 32;

#pragma unroll
    for (int it = 0; it < 4; it++) {
        const int r = fr + 32 * it;
        cp_async16(asBase + (r * GB32 + fg * 4) * 4, &A[(size_t)(rowBase + r) * K + fg * 8]);
        cp_async16(bsBase + (r * GB32 + fg * 4) * 4, &BT[(size_t)(colBase + r) * K + fg * 8]);
    }
    CP_COMMIT();

    for (int st = 0; st < nst; st++) {
        const int buf = st & 1;
        if (st + 1 < nst) {
            const int nb = buf ^ 1;
            const int kt = (st + 1) * 32;
#pragma unroll
            for (int it = 0; it < 4; it++) {
                const int r = fr + 32 * it;
                cp_async16(asBase + (nb * GBUFU + r * GB32 + fg * 4) * 4,
                           &A[(size_t)(rowBase + r) * K + kt + fg * 8]);
                cp_async16(bsBase + (nb * GBUFU + r * GB32 + fg * 4) * 4,
                           &BT[(size_t)(colBase + r) * K + kt + fg * 8]);
            }
            CP_COMMIT();
            CP_WAIT(1);
        } else {
            CP_WAIT(0);
        }
        __syncthreads();

        const uint4* A4 = (const uint4*)(As + buf * GBUFU);
        const uint4* B4 = (const uint4*)(Bs + buf * GBUFU);

        uint4 a0[4], a1[4];
#pragma unroll
        for (int mi = 0; mi < 4; mi++) {
            const int r0 = wm * 64 + mi * 16 + gid;
            a0[mi] = A4[r0 * 4 + tig];
            a1[mi] = A4[(r0 + 8) * 4 + tig];
        }
#pragma unroll
        for (int ni = 0; ni < 8; ni++) {
            const int c0 = wn * 64 + ni * 8 + gid;
            const uint4 bv = B4[c0 * 4 + tig];
#pragma unroll
            for (int mi = 0; mi < 4; mi++) {
                uint32_t af[4], bf[2];
                af[0] = a0[mi].x; af[1] = a1[mi].x;
                af[2] = a0[mi].y; af[3] = a1[mi].y;
                bf[0] = bv.x; bf[1] = bv.y;
                mma_f16(acc[mi][ni], af, bf);
                af[0] = a0[mi].z; af[1] = a1[mi].z;
                af[2] = a0[mi].w; af[3] = a1[mi].w;
                bf[0] = bv.z; bf[1] = bv.w;
                mma_f16(acc[mi][ni], af, bf);
            }
        }
        __syncthreads();
    }

    // ---- epilogue
#pragma unroll
    for (int mi = 0; mi < 4; mi++) {
#pragma unroll
        for (int ni = 0; ni < 8; ni++) {
            const int row0 = rowBase + wm * 64 + mi * 16 + gid;
            const int col  = colBase + wn * 64 + ni * 8 + tig * 2;
            if (OUT_HALF) {
                __half* C = (__half*)Cv;
                *(uint32_t*)&C[(size_t)row0 * N + col] =
                    packh2(acc[mi][ni][0], acc[mi][ni][1]);
                *(uint32_t*)&C[(size_t)(row0 + 8) * N + col] =
                    packh2(acc[mi][ni][2], acc[mi][ni][3]);
            } else {
                float* C = (float*)Cv;
                float b0 = 0.f, b1 = 0.f;
                if (bias) { b0 = bias[col]; b1 = bias[col + 1]; }
                float2 v0, v1;
                v0.x = acc[mi][ni][0] + b0; v0.y = acc[mi][ni][1] + b1;
                v1.x = acc[mi][ni][2] + b0; v1.y = acc[mi][ni][3] + b1;
                *(float2*)&C[(size_t)row0 * N + col] = v0;
                *(float2*)&C[(size_t)(row0 + 8) * N + col] = v1;
            }
        }
    }
}

// ---------------------------------------------------------------------------
// fp16 flash-style block-local attention.
// CTA: 128 q rows of one (b,h,chunk); 8 warps x 16 q. 16 key tiles of 64.
// K smem [64 key][32 d] fp16 (natural). V smem transposed [32 d][64 key] fp16
// with granule-XOR swizzle (col_b32 ^ ((d&7)<<2)). S C-frag == PV A-frag.
// Softmax in log2 domain with SCALE folded in (no q scaling).
// Grid = 4*8*4*8 = 1024 CTAs, 256 threads.
// ---------------------------------------------------------------------------
__global__ void __launch_bounds__(256)
attn_f16(const __half* __restrict__ qkv, __half* __restrict__ o_out)
{
    __shared__ uint4    sk4[2][64 * 4];   // K tiles: granule = key*4 + dgrp
    __shared__ uint32_t svt[2][32 * 32];  // V^T b32, swizzled

    const int bx = blockIdx.x;
    const int qt = bx & 7;
    const int c  = (bx >> 3) & 3;
    const int h  = (bx >> 5) & 7;
    const int b  = bx >> 8;

    const int tid  = threadIdx.x;
    const int wid  = tid >> 5;
    const int lane = tid & 31;
    const int gid  = lane >> 2;
    const int tig  = lane & 3;

    const size_t rowbase = (size_t)b * NTOK + (size_t)c * BLKTOK;

    // ---- Q fragments: 2 uint4 (rows gid, gid+8), b32 offset 4*tig (d = 8*tig)
    const int q0 = qt * 128 + wid * 16;
    uint4 qa0, qa1;
    {
        const __half* qp0 = qkv + (rowbase + q0 + gid) * QKVD + h * HD;
        const __half* qp1 = qkv + (rowbase + q0 + gid + 8) * QKVD + h * HD;
        qa0 = *(const uint4*)(qp0 + 8 * tig);
        qa1 = *(const uint4*)(qp1 + 8 * tig);
    }

    // loader indices
    const int keyl = tid >> 2;        // 0..63
    const int dgrp = tid & 3;         // 0..3
    const int d0   = dgrp * 8;

    // ---- load tile 0
    {
        const __half* kp = qkv + (rowbase + keyl) * QKVD + CDIM + h * HD;
        const uint4 kv = *(const uint4*)(kp + d0);
        const uint4 vv = *(const uint4*)(kp + CDIM + d0);
        sk4[0][keyl * 4 + dgrp] = kv;
        const __half* vh = (const __half*)&vv;
        __half* sv = (__half*)svt[0];
#pragma unroll
        for (int j = 0; j < 8; j++)
            sv[(d0 + j) * 64 + (((keyl >> 1) ^ (j << 2)) << 1) + (keyl & 1)] = vh[j];
    }
    __syncthreads();

    float m0 = -1e30f, m1 = -1e30f, l0 = 0.0f, l1 = 0.0f;
    float o[4][4];
#pragma unroll
    for (int ni = 0; ni < 4; ni++)
#pragma unroll
        for (int r = 0; r < 4; r++) o[ni][r] = 0.0f;

    for (int kt = 0; kt < 16; kt++) {
        const int buf = kt & 1;

        // prefetch next tile
        uint4 kv, vv;
        if (kt < 15) {
            const __half* kp = qkv + (rowbase + (kt + 1) * 64 + keyl) * QKVD + CDIM + h * HD;
            kv = *(const uint4*)(kp + d0);
            vv = *(const uint4*)(kp + CDIM + d0);
        }

        // ---- S = Q @ K^T (raw scores, 16 x 64 per warp)
        float s[8][4];
#pragma unroll
        for (int nj = 0; nj < 8; nj++) {
#pragma unroll
            for (int r = 0; r < 4; r++) s[nj][r] = 0.0f;
            const uint4 kb = sk4[buf][(nj * 8 + gid) * 4 + tig];
            uint32_t af[4], bf[2];
            af[0] = qa0.x; af[1] = qa1.x; af[2] = qa0.y; af[3] = qa1.y;
            bf[0] = kb.x;  bf[1] = kb.y;
            mma_f16(s[nj], af, bf);
            af[0] = qa0.z; af[1] = qa1.z; af[2] = qa0.w; af[3] = qa1.w;
            bf[0] = kb.z;  bf[1] = kb.w;
            mma_f16(s[nj], af, bf);
        }

        // ---- online softmax (log2 domain, SCALE folded)
        float tmax0 = -1e30f, tmax1 = -1e30f;
#pragma unroll
        for (int nj = 0; nj < 8; nj++) {
            tmax0 = fmaxf(tmax0, fmaxf(s[nj][0], s[nj][1]));
            tmax1 = fmaxf(tmax1, fmaxf(s[nj][2], s[nj][3]));
        }
        tmax0 = fmaxf(tmax0, __shfl_xor_sync(0xffffffffu, tmax0, 1));
        tmax0 = fmaxf(tmax0, __shfl_xor_sync(0xffffffffu, tmax0, 2));
        tmax1 = fmaxf(tmax1, __shfl_xor_sync(0xffffffffu, tmax1, 1));
        tmax1 = fmaxf(tmax1, __shfl_xor_sync(0xffffffffu, tmax1, 2));

        const float m0n = fmaxf(m0, tmax0);
        const float m1n = fmaxf(m1, tmax1);
        const float a0 = exp2f((m0 - m0n) * C2LOG);
        const float a1 = exp2f((m1 - m1n) * C2LOG);
        m0 = m0n; m1 = m1n;

        float sum0 = 0.0f, sum1 = 0.0f;
#pragma unroll
        for (int nj = 0; nj < 8; nj++) {
            s[nj][0] = exp2f((s[nj][0] - m0) * C2LOG);
            s[nj][1] = exp2f((s[nj][1] - m0) * C2LOG);
            s[nj][2] = exp2f((s[nj][2] - m1) * C2LOG);
            s[nj][3] = exp2f((s[nj][3] - m1) * C2LOG);
            sum0 += s[nj][0] + s[nj][1];
            sum1 += s[nj][2] + s[nj][3];
        }
        l0 = l0 * a0 + sum0;
        l1 = l1 * a1 + sum1;
#pragma unroll
        for (int ni = 0; ni < 4; ni++) {
            o[ni][0] *= a0; o[ni][1] *= a0;
            o[ni][2] *= a1; o[ni][3] *= a1;
        }

        // ---- O += P @ V  (S C-frag == PV A-frag; pack to half2 in-register)
        const uint32_t* vb = svt[buf];
#pragma unroll
        for (int t = 0; t < 4; t++) {
            uint32_t af[4];
            af[0] = packh2(s[2 * t][0],     s[2 * t][1]);
            af[1] = packh2(s[2 * t][2],     s[2 * t][3]);
            af[2] = packh2(s[2 * t + 1][0], s[2 * t + 1][1]);
            af[3] = packh2(s[2 * t + 1][2], s[2 * t + 1][3]);
            const int sw = gid << 2;
#pragma unroll
            for (int ni = 0; ni < 4; ni++) {
                const int d = ni * 8 + gid;
                uint32_t bf[2];
                bf[0] = vb[d * 32 + ((8 * t + tig)     ^ sw)];
                bf[1] = vb[d * 32 + ((8 * t + tig + 4) ^ sw)];
                mma_f16(o[ni], af, bf);
            }
        }

        // ---- stage next tile
        if (kt < 15) {
            const int nb = buf ^ 1;
            sk4[nb][keyl * 4 + dgrp] = kv;
            const __half* vh = (const __half*)&vv;
            __half* sv = (__half*)svt[nb];
#pragma unroll
            for (int j = 0; j < 8; j++)
                sv[(d0 + j) * 64 + (((keyl >> 1) ^ (j << 2)) << 1) + (keyl & 1)] = vh[j];
        }
        __syncthreads();
    }

    // ---- finalize
    l0 += __shfl_xor_sync(0xffffffffu, l0, 1);
    l0 += __shfl_xor_sync(0xffffffffu, l0, 2);
    l1 += __shfl_xor_sync(0xffffffffu, l1, 1);
    l1 += __shfl_xor_sync(0xffffffffu, l1, 2);
    const float inv0 = 1.0f / l0;
    const float inv1 = 1.0f / l1;

    __half* op0 = o_out + (rowbase + q0 + gid) * CDIM + h * HD;
    __half* op1 = o_out + (rowbase + q0 + gid + 8) * CDIM + h * HD;
#pragma unroll
    for (int ni = 0; ni < 4; ni++) {
        *(uint32_t*)(op0 + ni * 8 + tig * 2) = packh2(o[ni][0] * inv0, o[ni][1] * inv0);
        *(uint32_t*)(op1 + ni * 8 + tig * 2) = packh2(o[ni][2] * inv1, o[ni][3] * inv1);
    }
}

// ---------------------------------------------------------------------------
// Launch
// ---------------------------------------------------------------------------
extern "C" void kernel_launch(void* const* d_in, const int* in_sizes, int n_in,
                              void* d_out, int out_size)
{
    const float* x    = (const float*)d_in[0];
    const float* Wd   = (const float*)d_in[1];
    const float* Wqkv = (const float*)d_in[2];
    const float* Wup  = (const float*)d_in[3];
    const float* bup  = (const float*)d_in[4];
    float* out = (float*)d_out;

    __half *px16, *ph16, *pqkv16, *po16, *pwdT, *pwqkvT, *pwupT;
    cudaGetSymbolAddress((void**)&px16,   g_x16);
    cudaGetSymbolAddress((void**)&ph16,   g_h16);
    cudaGetSymbolAddress((void**)&pqkv16, g_qkv16);
    cudaGetSymbolAddress((void**)&po16,   g_o16);
    cudaGetSymbolAddress((void**)&pwdT,   g_wdT);
    cudaGetSymbolAddress((void**)&pwqkvT, g_wqkvT);
    cudaGetSymbolAddress((void**)&pwupT,  g_wupT);

    cudaFuncSetAttribute(gemm_f16<true>,
                         cudaFuncAttributeMaxDynamicSharedMemorySize, GEMM_SMEM_BYTES);
    cudaFuncSetAttribute(gemm_f16<false>,
                         cudaFuncAttributeMaxDynamicSharedMemorySize, GEMM_SMEM_BYTES);

    // prologue: x -> fp16, weights -> K-major fp16
    cvt_f32_f16<<<(M_TOTAL * INCH) / (256 * 8), 256>>>(x, px16, M_TOTAL * INCH);
    {
        dim3 blk(32, 8);
        transpose_f16<<<dim3(INCH / 32, CDIM / 32), blk>>>(Wd,   pwdT,   INCH, CDIM);
        transpose_f16<<<dim3(CDIM / 32, QKVD / 32), blk>>>(Wqkv, pwqkvT, CDIM, QKVD);
        transpose_f16<<<dim3(CDIM / 32, INCH / 32), blk>>>(Wup,  pwupT,  CDIM, INCH);
    }

    // GEMM1: h16 = x16 @ Wd
    {
        dim3 grid(CDIM / 128, M_TOTAL / 128);
        gemm_f16<true><<<grid, 128, GEMM_SMEM_BYTES>>>(px16, pwdT, nullptr, ph16,
                                                       M_TOTAL, CDIM, INCH);
    }
    // GEMM2: qkv16 = h16 @ Wqkv
    {
        dim3 grid(QKVD / 128, M_TOTAL / 128);
        gemm_f16<true><<<grid, 128, GEMM_SMEM_BYTES>>>(ph16, pwqkvT, nullptr, pqkv16,
                                                       M_TOTAL, QKVD, CDIM);
    }
    // attention
    attn_f16<<<BATCH * HEADS * CUT * (BLKTOK / 128), 256>>>(pqkv16, po16);
    // GEMM3: out = o16 @ Wup + bup (fp32 out)
    {
        dim3 grid(INCH / 128, M_TOTAL / 128);
        gemm_f16<false><<<grid, 128, GEMM_SMEM_BYTES>>>(po16, pwupT, bup, out,
                                                        M_TOTAL, INCH, CDIM);
    }
}

// round 8
// speedup vs baseline: 20.5844x; 1.0726x over previous
#include <cuda_runtime.h>
#include <cuda_fp16.h>
#include <stdint.h>
#include <math.h>

// ---------------------------------------------------------------------------
// Problem constants
// ---------------------------------------------------------------------------
#define BATCH   4
#define NTOK    4096
#define INCH    1280
#define CDIM    256
#define QKVD    768
#define HEADS   8
#define HD      32
#define CUT     4
#define BLKTOK  1024
#define M_TOTAL (BATCH*NTOK)
#define SCALE_F 0.07905694150420949f   // 160^-0.5
#define C2LOG   (SCALE_F * 1.4426950408889634f)   // SCALE * log2(e)

// ---------------------------------------------------------------------------
// Scratch (fp16 operand world, fp32 final out)
// ---------------------------------------------------------------------------
__device__ __half g_x16[M_TOTAL * INCH];
__device__ __half g_h16[M_TOTAL * CDIM];
__device__ __half g_qkv16[M_TOTAL * QKVD];
__device__ __half g_o16[M_TOTAL * CDIM];
__device__ __half g_wdT[CDIM * INCH];     // K-major [256][1280]
__device__ __half g_wqkvT[QKVD * CDIM];   // [768][256]
__device__ __half g_wupT[INCH * CDIM];    // [1280][256]

// ---------------------------------------------------------------------------
// helpers
// ---------------------------------------------------------------------------
__device__ __forceinline__ void mma_f16(float* d, const uint32_t* a, const uint32_t* b) {
    asm volatile(
        "mma.sync.aligned.m16n8k16.row.col.f32.f16.f16.f32 "
        "{%0,%1,%2,%3}, {%4,%5,%6,%7}, {%8,%9}, {%0,%1,%2,%3};"
        : "+f"(d[0]), "+f"(d[1]), "+f"(d[2]), "+f"(d[3])
        : "r"(a[0]), "r"(a[1]), "r"(a[2]), "r"(a[3]), "r"(b[0]), "r"(b[1]));
}
__device__ __forceinline__ uint32_t smem_u32(const void* p) {
    uint32_t a;
    asm("{ .reg .u64 t; cvta.to.shared.u64 t, %1; cvt.u32.u64 %0, t; }" : "=r"(a) : "l"(p));
    return a;
}
__device__ __forceinline__ void cp_async16(uint32_t dst, const void* src) {
    asm volatile("cp.async.cg.shared.global [%0], [%1], 16;" :: "r"(dst), "l"(src));
}
#define CP_COMMIT() asm volatile("cp.async.commit_group;" ::: "memory")
#define CP_WAIT(n)  asm volatile("cp.async.wait_group %0;" :: "n"(n) : "memory")

__device__ __forceinline__ uint32_t packh2(float lo, float hi) {
    __half2 h = __floats2half2_rn(lo, hi);
    return *(uint32_t*)&h;
}
__device__ __forceinline__ uint32_t h2ex2(uint32_t h2) {
    uint32_t r;
    asm("ex2.approx.f16x2 %0, %1;" : "=r"(r) : "r"(h2));
    return r;
}

// ---------------------------------------------------------------------------
// fp32 -> fp16 conversion (vector 8)
// ---------------------------------------------------------------------------
__global__ void cvt_f32_f16(const float* __restrict__ s, __half* __restrict__ d, int n)
{
    const int i = (blockIdx.x * 256 + threadIdx.x) * 8;
    if (i < n) {
        float4 v0 = *(const float4*)(s + i);
        float4 v1 = *(const float4*)(s + i + 4);
        uint4 o;
        o.x = packh2(v0.x, v0.y);
        o.y = packh2(v0.z, v0.w);
        o.z = packh2(v1.x, v1.y);
        o.w = packh2(v1.z, v1.w);
        *(uint4*)(d + i) = o;
    }
}

// ---------------------------------------------------------------------------
// Weight transpose fp32 -> fp16 K-major: WT[n][k] = (half)W[k][n]
// ---------------------------------------------------------------------------
__global__ void transpose_f16(const float* __restrict__ W, __half* __restrict__ WT,
                              int K, int N)
{
    __shared__ float t[32][33];
    const int kb = blockIdx.x * 32, nb = blockIdx.y * 32;
    const int tx = threadIdx.x, ty = threadIdx.y;   // 32 x 8
#pragma unroll
    for (int i = 0; i < 4; i++)
        t[ty + 8 * i][tx] = W[(size_t)(kb + ty + 8 * i) * N + nb + tx];
    __syncthreads();
#pragma unroll
    for (int i = 0; i < 4; i++)
        WT[(size_t)(nb + ty + 8 * i) * K + kb + tx] = __float2half_rn(t[tx][ty + 8 * i]);
}

// ---------------------------------------------------------------------------
// fp16 tensor-core GEMM: C = A[M,K] @ BT[N,K]^T (+bias).
// CTA 128x128, 4 warps (2x2), warp 64x64. K staged 32 halves (16 b32).
// 3-stage cp.async ring, ONE __syncthreads per stage.
// ---------------------------------------------------------------------------
#define GB32  16                      // b32 per row per stage
#define GBUFU (128 * GB32)            // b32 per operand buffer
#define GEMM_SMEM_BYTES (6 * GBUFU * 4)   // 3 stages x (A+B) = 49152

template<bool OUT_HALF>
__global__ void __launch_bounds__(128, 2)
gemm_f16(const __half* __restrict__ A, const __half* __restrict__ BT,
         const float* __restrict__ bias, void* __restrict__ Cv,
         int M, int N, int K)
{
    extern __shared__ uint32_t smem[];

    const int tid  = threadIdx.x;
    const int wid  = tid >> 5;
    const int lane = tid & 31;
    const int gid  = lane >> 2;
    const int tig  = lane & 3;
    const int wm   = wid >> 1;
    const int wn   = wid & 1;
    const int rowBase = blockIdx.y * 128;
    const int colBase = blockIdx.x * 128;

    float acc[4][8][4];
#pragma unroll
    for (int mi = 0; mi < 4; mi++)
#pragma unroll
        for (int ni = 0; ni < 8; ni++)
#pragma unroll
            for (int r = 0; r < 4; r++) acc[mi][ni][r] = 0.0f;

    const int fr = tid >> 2;          // 0..31, 4 iters -> 128 rows
    const int fg = tid & 3;           // granule 0..3 (8 halves)

    const uint32_t sBase = smem_u32(smem);
    const int nst = K / 32;

    auto issue = [&](int st, int sb) {
        const int kt = st * 32;
        const uint32_t ab = sBase + (sb * 2 * GBUFU) * 4;
        const uint32_t bb = ab + GBUFU * 4;
#pragma unroll
        for (int it = 0; it < 4; it++) {
            const int r = fr + 32 * it;
            cp_async16(ab + (r * GB32 + fg * 4) * 4, &A[(size_t)(rowBase + r) * K + kt + fg * 8]);
            cp_async16(bb + (r * GB32 + fg * 4) * 4, &BT[(size_t)(colBase + r) * K + kt + fg * 8]);
        }
        CP_COMMIT();
    };

    issue(0, 0);
    if (nst > 1) issue(1, 1);

    int rb = 0;
    for (int st = 0; st < nst; st++) {
        if (st + 1 < nst) { CP_WAIT(1); } else { CP_WAIT(0); }
        __syncthreads();
        if (st + 2 < nst) {
            const int sb = (rb + 2 >= 3) ? rb - 1 : rb + 2;
            issue(st + 2, sb);
        }

        const uint4* A4 = (const uint4*)(smem + rb * 2 * GBUFU);
        const uint4* B4 = (const uint4*)(smem + rb * 2 * GBUFU + GBUFU);

        uint4 a0[4], a1[4];
#pragma unroll
        for (int mi = 0; mi < 4; mi++) {
            const int r0 = wm * 64 + mi * 16 + gid;
            a0[mi] = A4[r0 * 4 + tig];
            a1[mi] = A4[(r0 + 8) * 4 + tig];
        }
#pragma unroll
        for (int ni = 0; ni < 8; ni++) {
            const int c0 = wn * 64 + ni * 8 + gid;
            const uint4 bv = B4[c0 * 4 + tig];
#pragma unroll
            for (int mi = 0; mi < 4; mi++) {
                uint32_t af[4], bf[2];
                af[0] = a0[mi].x; af[1] = a1[mi].x;
                af[2] = a0[mi].y; af[3] = a1[mi].y;
                bf[0] = bv.x; bf[1] = bv.y;
                mma_f16(acc[mi][ni], af, bf);
                af[0] = a0[mi].z; af[1] = a1[mi].z;
                af[2] = a0[mi].w; af[3] = a1[mi].w;
                bf[0] = bv.z; bf[1] = bv.w;
                mma_f16(acc[mi][ni], af, bf);
            }
        }
        rb = (rb + 1 == 3) ? 0 : rb + 1;
    }

    // ---- epilogue
#pragma unroll
    for (int mi = 0; mi < 4; mi++) {
#pragma unroll
        for (int ni = 0; ni < 8; ni++) {
            const int row0 = rowBase + wm * 64 + mi * 16 + gid;
            const int col  = colBase + wn * 64 + ni * 8 + tig * 2;
            if (OUT_HALF) {
                __half* C = (__half*)Cv;
                *(uint32_t*)&C[(size_t)row0 * N + col] =
                    packh2(acc[mi][ni][0], acc[mi][ni][1]);
                *(uint32_t*)&C[(size_t)(row0 + 8) * N + col] =
                    packh2(acc[mi][ni][2], acc[mi][ni][3]);
            } else {
                float* C = (float*)Cv;
                float b0 = 0.f, b1 = 0.f;
                if (bias) { b0 = bias[col]; b1 = bias[col + 1]; }
                float2 v0, v1;
                v0.x = acc[mi][ni][0] + b0; v0.y = acc[mi][ni][1] + b1;
                v1.x = acc[mi][ni][2] + b0; v1.y = acc[mi][ni][3] + b1;
                *(float2*)&C[(size_t)row0 * N + col] = v0;
                *(float2*)&C[(size_t)(row0 + 8) * N + col] = v1;
            }
        }
    }
}

// ---------------------------------------------------------------------------
// fp16 flash attention; ex2.approx.f16x2 softmax, l via ones-column MMA.
// CTA: 128 q rows of one (b,h,chunk); 8 warps x 16 q. 16 key tiles of 64.
// ---------------------------------------------------------------------------
__global__ void __launch_bounds__(256)
attn_f16(const __half* __restrict__ qkv, __half* __restrict__ o_out)
{
    __shared__ uint4    sk4[2][64 * 4];   // K tiles: granule = key*4 + dgrp
    __shared__ uint32_t svt[2][32 * 32];  // V^T b32, swizzled

    const int bx = blockIdx.x;
    const int qt = bx & 7;
    const int c  = (bx >> 3) & 3;
    const int h  = (bx >> 5) & 7;
    const int b  = bx >> 8;

    const int tid  = threadIdx.x;
    const int wid  = tid >> 5;
    const int lane = tid & 31;
    const int gid  = lane >> 2;
    const int tig  = lane & 3;

    const size_t rowbase = (size_t)b * NTOK + (size_t)c * BLKTOK;

    const int q0 = qt * 128 + wid * 16;
    uint4 qa0, qa1;
    {
        const __half* qp0 = qkv + (rowbase + q0 + gid) * QKVD + h * HD;
        const __half* qp1 = qkv + (rowbase + q0 + gid + 8) * QKVD + h * HD;
        qa0 = *(const uint4*)(qp0 + 8 * tig);
        qa1 = *(const uint4*)(qp1 + 8 * tig);
    }

    const int keyl = tid >> 2;        // 0..63
    const int dgrp = tid & 3;         // 0..3
    const int d0   = dgrp * 8;

    {
        const __half* kp = qkv + (rowbase + keyl) * QKVD + CDIM + h * HD;
        const uint4 kv = *(const uint4*)(kp + d0);
        const uint4 vv = *(const uint4*)(kp + CDIM + d0);
        sk4[0][keyl * 4 + dgrp] = kv;
        const __half* vh = (const __half*)&vv;
        __half* sv = (__half*)svt[0];
#pragma unroll
        for (int j = 0; j < 8; j++)
            sv[(d0 + j) * 64 + (((keyl >> 1) ^ (j << 2)) << 1) + (keyl & 1)] = vh[j];
    }
    __syncthreads();

    float m0 = -1e30f, m1 = -1e30f;
    float lacc[4];
    float o[4][4];
#pragma unroll
    for (int r = 0; r < 4; r++) lacc[r] = 0.0f;
#pragma unroll
    for (int ni = 0; ni < 4; ni++)
#pragma unroll
        for (int r = 0; r < 4; r++) o[ni][r] = 0.0f;

    const uint32_t ONES = 0x3C003C00u;

    for (int kt = 0; kt < 16; kt++) {
        const int buf = kt & 1;

        uint4 kv, vv;
        if (kt < 15) {
            const __half* kp = qkv + (rowbase + (kt + 1) * 64 + keyl) * QKVD + CDIM + h * HD;
            kv = *(const uint4*)(kp + d0);
            vv = *(const uint4*)(kp + CDIM + d0);
        }

        // ---- S = Q @ K^T (raw scores)
        float s[8][4];
#pragma unroll
        for (int nj = 0; nj < 8; nj++) {
#pragma unroll
            for (int r = 0; r < 4; r++) s[nj][r] = 0.0f;
            const uint4 kb = sk4[buf][(nj * 8 + gid) * 4 + tig];
            uint32_t af[4], bf[2];
            af[0] = qa0.x; af[1] = qa1.x; af[2] = qa0.y; af[3] = qa1.y;
            bf[0] = kb.x;  bf[1] = kb.y;
            mma_f16(s[nj], af, bf);
            af[0] = qa0.z; af[1] = qa1.z; af[2] = qa0.w; af[3] = qa1.w;
            bf[0] = kb.z;  bf[1] = kb.w;
            mma_f16(s[nj], af, bf);
        }

        // ---- online max
        float tmax0 = -1e30f, tmax1 = -1e30f;
#pragma unroll
        for (int nj = 0; nj < 8; nj++) {
            tmax0 = fmaxf(tmax0, fmaxf(s[nj][0], s[nj][1]));
            tmax1 = fmaxf(tmax1, fmaxf(s[nj][2], s[nj][3]));
        }
        tmax0 = fmaxf(tmax0, __shfl_xor_sync(0xffffffffu, tmax0, 1));
        tmax0 = fmaxf(tmax0, __shfl_xor_sync(0xffffffffu, tmax0, 2));
        tmax1 = fmaxf(tmax1, __shfl_xor_sync(0xffffffffu, tmax1, 1));
        tmax1 = fmaxf(tmax1, __shfl_xor_sync(0xffffffffu, tmax1, 2));

        const float m0n = fmaxf(m0, tmax0);
        const float m1n = fmaxf(m1, tmax1);
        const float a0 = exp2f((m0 - m0n) * C2LOG);
        const float a1 = exp2f((m1 - m1n) * C2LOG);
        m0 = m0n; m1 = m1n;
        const float mc0 = m0 * C2LOG;
        const float mc1 = m1 * C2LOG;

        lacc[0] *= a0; lacc[1] *= a0; lacc[2] *= a1; lacc[3] *= a1;
#pragma unroll
        for (int ni = 0; ni < 4; ni++) {
            o[ni][0] *= a0; o[ni][1] *= a0;
            o[ni][2] *= a1; o[ni][3] *= a1;
        }

        // ---- P = exp(s - m) via ex2.approx.f16x2; pf == PV A-frags
        uint32_t pf[8][2];
#pragma unroll
        for (int nj = 0; nj < 8; nj++) {
            const float t0 = fmaf(s[nj][0], C2LOG, -mc0);
            const float t1 = fmaf(s[nj][1], C2LOG, -mc0);
            const float t2 = fmaf(s[nj][2], C2LOG, -mc1);
            const float t3 = fmaf(s[nj][3], C2LOG, -mc1);
            pf[nj][0] = h2ex2(packh2(t0, t1));
            pf[nj][1] = h2ex2(packh2(t2, t3));
        }

        // ---- O += P @ V ; l += P @ ones
        const uint32_t* vb = svt[buf];
#pragma unroll
        for (int t = 0; t < 4; t++) {
            uint32_t af[4];
            af[0] = pf[2 * t][0];
            af[1] = pf[2 * t][1];
            af[2] = pf[2 * t + 1][0];
            af[3] = pf[2 * t + 1][1];
            uint32_t ob[2] = { ONES, ONES };
            mma_f16(lacc, af, ob);
            const int sw = gid << 2;
#pragma unroll
            for (int ni = 0; ni < 4; ni++) {
                const int d = ni * 8 + gid;
                uint32_t bf[2];
                bf[0] = vb[d * 32 + ((8 * t + tig)     ^ sw)];
                bf[1] = vb[d * 32 + ((8 * t + tig + 4) ^ sw)];
                mma_f16(o[ni], af, bf);
            }
        }

        // ---- stage next tile
        if (kt < 15) {
            const int nb = buf ^ 1;
            sk4[nb][keyl * 4 + dgrp] = kv;
            const __half* vh = (const __half*)&vv;
            __half* sv = (__half*)svt[nb];
#pragma unroll
            for (int j = 0; j < 8; j++)
                sv[(d0 + j) * 64 + (((keyl >> 1) ^ (j << 2)) << 1) + (keyl & 1)] = vh[j];
        }
        __syncthreads();
    }

    // ---- finalize: every lane already holds its row's l (ones columns)
    const float inv0 = 1.0f / lacc[0];
    const float inv1 = 1.0f / lacc[2];

    __half* op0 = o_out + (rowbase + q0 + gid) * CDIM + h * HD;
    __half* op1 = o_out + (rowbase + q0 + gid + 8) * CDIM + h * HD;
#pragma unroll
    for (int ni = 0; ni < 4; ni++) {
        *(uint32_t*)(op0 + ni * 8 + tig * 2) = packh2(o[ni][0] * inv0, o[ni][1] * inv0);
        *(uint32_t*)(op1 + ni * 8 + tig * 2) = packh2(o[ni][2] * inv1, o[ni][3] * inv1);
    }
}

// ---------------------------------------------------------------------------
// Launch
// ---------------------------------------------------------------------------
extern "C" void kernel_launch(void* const* d_in, const int* in_sizes, int n_in,
                              void* d_out, int out_size)
{
    const float* x    = (const float*)d_in[0];
    const float* Wd   = (const float*)d_in[1];
    const float* Wqkv = (const float*)d_in[2];
    const float* Wup  = (const float*)d_in[3];
    const float* bup  = (const float*)d_in[4];
    float* out = (float*)d_out;

    __half *px16, *ph16, *pqkv16, *po16, *pwdT, *pwqkvT, *pwupT;
    cudaGetSymbolAddress((void**)&px16,   g_x16);
    cudaGetSymbolAddress((void**)&ph16,   g_h16);
    cudaGetSymbolAddress((void**)&pqkv16, g_qkv16);
    cudaGetSymbolAddress((void**)&po16,   g_o16);
    cudaGetSymbolAddress((void**)&pwdT,   g_wdT);
    cudaGetSymbolAddress((void**)&pwqkvT, g_wqkvT);
    cudaGetSymbolAddress((void**)&pwupT,  g_wupT);

    cudaFuncSetAttribute(gemm_f16<true>,
                         cudaFuncAttributeMaxDynamicSharedMemorySize, GEMM_SMEM_BYTES);
    cudaFuncSetAttribute(gemm_f16<false>,
                         cudaFuncAttributeMaxDynamicSharedMemorySize, GEMM_SMEM_BYTES);

    // prologue: x -> fp16, weights -> K-major fp16
    cvt_f32_f16<<<(M_TOTAL * INCH) / (256 * 8), 256>>>(x, px16, M_TOTAL * INCH);
    {
        dim3 blk(32, 8);
        transpose_f16<<<dim3(INCH / 32, CDIM / 32), blk>>>(Wd,   pwdT,   INCH, CDIM);
        transpose_f16<<<dim3(CDIM / 32, QKVD / 32), blk>>>(Wqkv, pwqkvT, CDIM, QKVD);
        transpose_f16<<<dim3(CDIM / 32, INCH / 32), blk>>>(Wup,  pwupT,  CDIM, INCH);
    }

    // GEMM1: h16 = x16 @ Wd
    {
        dim3 grid(CDIM / 128, M_TOTAL / 128);
        gemm_f16<true><<<grid, 128, GEMM_SMEM_BYTES>>>(px16, pwdT, nullptr, ph16,
                                                       M_TOTAL, CDIM, INCH);
    }
    // GEMM2: qkv16 = h16 @ Wqkv
    {
        dim3 grid(QKVD / 128, M_TOTAL / 128);
        gemm_f16<true><<<grid, 128, GEMM_SMEM_BYTES>>>(ph16, pwqkvT, nullptr, pqkv16,
                                                       M_TOTAL, QKVD, CDIM);
    }
    // attention
    attn_f16<<<BATCH * HEADS * CUT * (BLKTOK / 128), 256>>>(pqkv16, po16);
    // GEMM3: out = o16 @ Wup + bup (fp32 out)
    {
        dim3 grid(INCH / 128, M_TOTAL / 128);
        gemm_f16<false><<<grid, 128, GEMM_SMEM_BYTES>>>(po16, pwupT, bup, out,
                                                        M_TOTAL, INCH, CDIM);
    }
}

// round 9
// speedup vs baseline: 22.2723x; 1.0820x over previous
#include <cuda_runtime.h>
#include <cuda_fp16.h>
#include <stdint.h>
#include <math.h>

// ---------------------------------------------------------------------------
// Problem constants
// ---------------------------------------------------------------------------
#define BATCH   4
#define NTOK    4096
#define INCH    1280
#define CDIM    256
#define QKVD    768
#define HEADS   8
#define HD      32
#define CUT     4
#define BLKTOK  1024
#define M_TOTAL (BATCH*NTOK)
#define SCALE_F 0.07905694150420949f   // 160^-0.5
#define C2LOG   (SCALE_F * 1.4426950408889634f)   // SCALE * log2(e)

// ---------------------------------------------------------------------------
// Scratch
// ---------------------------------------------------------------------------
__device__ __half g_h16[M_TOTAL * CDIM];
__device__ __half g_qkv16[M_TOTAL * QKVD];
__device__ __half g_o16[M_TOTAL * CDIM];
__device__ __half g_wdT[CDIM * INCH];     // K-major [256][1280]
__device__ __half g_wqkvT[QKVD * CDIM];   // [768][256]
__device__ __half g_wupT[INCH * CDIM];    // [1280][256]

// ---------------------------------------------------------------------------
// helpers
// ---------------------------------------------------------------------------
__device__ __forceinline__ void mma_f16(float* d, const uint32_t* a, const uint32_t* b) {
    asm volatile(
        "mma.sync.aligned.m16n8k16.row.col.f32.f16.f16.f32 "
        "{%0,%1,%2,%3}, {%4,%5,%6,%7}, {%8,%9}, {%0,%1,%2,%3};"
        : "+f"(d[0]), "+f"(d[1]), "+f"(d[2]), "+f"(d[3])
        : "r"(a[0]), "r"(a[1]), "r"(a[2]), "r"(a[3]), "r"(b[0]), "r"(b[1]));
}
__device__ __forceinline__ uint32_t smem_u32(const void* p) {
    uint32_t a;
    asm("{ .reg .u64 t; cvta.to.shared.u64 t, %1; cvt.u32.u64 %0, t; }" : "=r"(a) : "l"(p));
    return a;
}
__device__ __forceinline__ void cp_async16(uint32_t dst, const void* src) {
    asm volatile("cp.async.cg.shared.global [%0], [%1], 16;" :: "r"(dst), "l"(src));
}
#define CP_COMMIT() asm volatile("cp.async.commit_group;" ::: "memory")
#define CP_WAIT(n)  asm volatile("cp.async.wait_group %0;" :: "n"(n) : "memory")

__device__ __forceinline__ uint32_t packh2(float lo, float hi) {
    __half2 h = __floats2half2_rn(lo, hi);
    return *(uint32_t*)&h;
}
__device__ __forceinline__ uint32_t h2ex2(uint32_t h2) {
    uint32_t r;
    asm("ex2.approx.f16x2 %0, %1;" : "=r"(r) : "r"(h2));
    return r;
}

// ---------------------------------------------------------------------------
// Fused weight transposes fp32 -> fp16 K-major (one launch, 3 segments)
// grids: Wd 40x8=320, Wqkv 8x24=192, Wup 8x40=320 -> 832 blocks of (32,8)
// ---------------------------------------------------------------------------
__global__ void transpose_all(const float* __restrict__ Wd,
                              const float* __restrict__ Wqkv,
                              const float* __restrict__ Wup,
                              __half* __restrict__ wdT,
                              __half* __restrict__ wqkvT,
                              __half* __restrict__ wupT)
{
    __shared__ float t[32][33];
    const int bx = blockIdx.x;
    const float* W; __half* WT; int K, N, gx, base;
    if (bx < 320)      { W = Wd;   WT = wdT;   K = INCH; N = CDIM; gx = 40; base = 0; }
    else if (bx < 512) { W = Wqkv; WT = wqkvT; K = CDIM; N = QKVD; gx = 8;  base = 320; }
    else               { W = Wup;  WT = wupT;  K = CDIM; N = INCH; gx = 8;  base = 512; }
    const int i = bx - base;
    const int kb = (i % gx) * 32, nb = (i / gx) * 32;
    const int tx = threadIdx.x, ty = threadIdx.y;
#pragma unroll
    for (int r = 0; r < 4; r++)
        t[ty + 8 * r][tx] = W[(size_t)(kb + ty + 8 * r) * N + nb + tx];
    __syncthreads();
#pragma unroll
    for (int r = 0; r < 4; r++)
        WT[(size_t)(nb + ty + 8 * r) * K + kb + tx] = __float2half_rn(t[tx][ty + 8 * r]);
}

// ---------------------------------------------------------------------------
// GEMM1: h16[M,256] = x(fp32)[M,1280] @ WdT(fp16)[256,1280]^T
// CTA 128x256 (full N), 8 warps (2x4), warp 64x64, 256 threads, 1 CTA/SM.
// A staged fp32 [128][36] (stride 36: conflict-free LDS.128), cvt at consume.
// B staged fp16 [256][16 b32]. 3-stage cp.async ring. grid = M/128 = 128.
// ---------------------------------------------------------------------------
#define A1STRIDE 36
#define A1BUF (128 * A1STRIDE)          // floats per A stage
#define B1BUF (256 * 16)                // b32 per B stage
#define G1_SMEM_BYTES (3 * (A1BUF + B1BUF) * 4)   // 104448

__global__ void __launch_bounds__(256, 1)
gemm1_f16(const float* __restrict__ A, const __half* __restrict__ BT,
          __half* __restrict__ C)
{
    extern __shared__ uint32_t smem[];
    float*    As = (float*)smem;              // [3][128][36] fp32
    uint32_t* Bs = smem + 3 * A1BUF;          // [3][256][16] b32(h2)

    const int tid  = threadIdx.x;
    const int wid  = tid >> 5;
    const int lane = tid & 31;
    const int gid  = lane >> 2;
    const int tig  = lane & 3;
    const int wm   = wid >> 2;     // 0..1
    const int wn   = wid & 3;      // 0..3
    const int rowBase = blockIdx.x * 128;
    const int K = INCH, N = CDIM;

    float acc[4][8][4];
#pragma unroll
    for (int mi = 0; mi < 4; mi++)
#pragma unroll
        for (int ni = 0; ni < 8; ni++)
#pragma unroll
            for (int r = 0; r < 4; r++) acc[mi][ni][r] = 0.0f;

    const uint32_t asBase = smem_u32(As);
    const uint32_t bsBase = smem_u32(Bs);
    const int nst = K / 32;   // 40

    auto issue = [&](int st, int sb) {
        const int kt = st * 32;
        const uint32_t ab = asBase + (sb * A1BUF) * 4;
        const uint32_t bb = bsBase + (sb * B1BUF) * 4;
#pragma unroll
        for (int it = 0; it < 4; it++) {
            const int ch = tid + 256 * it;
            // A: 128 rows x 8 granules of 4 floats
            const int ar = ch >> 3, ag = ch & 7;
            cp_async16(ab + (ar * A1STRIDE + ag * 4) * 4,
                       &A[(size_t)(rowBase + ar) * K + kt + ag * 4]);
            // B: 256 rows x 4 granules of 8 halves
            const int br = ch >> 2, bg = ch & 3;
            cp_async16(bb + (br * 16 + bg * 4) * 4,
                       &BT[(size_t)br * K + kt + bg * 8]);
        }
        CP_COMMIT();
    };

    issue(0, 0);
    issue(1, 1);

    int rb = 0;
    for (int st = 0; st < nst; st++) {
        if (st + 1 < nst) { CP_WAIT(1); } else { CP_WAIT(0); }
        __syncthreads();
        if (st + 2 < nst) issue(st + 2, (rb + 2 >= 3) ? rb - 1 : rb + 2);

        const float* Ab = As + rb * A1BUF;
        const uint4* B4 = (const uint4*)(Bs + rb * B1BUF);

        uint4 a0[4], a1[4];
#pragma unroll
        for (int mi = 0; mi < 4; mi++) {
            const int r0 = wm * 64 + mi * 16 + gid;
            const float4 f0 = *(const float4*)(Ab + r0 * A1STRIDE + tig * 8);
            const float4 f1 = *(const float4*)(Ab + r0 * A1STRIDE + tig * 8 + 4);
            const float4 g0 = *(const float4*)(Ab + (r0 + 8) * A1STRIDE + tig * 8);
            const float4 g1 = *(const float4*)(Ab + (r0 + 8) * A1STRIDE + tig * 8 + 4);
            a0[mi].x = packh2(f0.x, f0.y); a0[mi].y = packh2(f0.z, f0.w);
            a0[mi].z = packh2(f1.x, f1.y); a0[mi].w = packh2(f1.z, f1.w);
            a1[mi].x = packh2(g0.x, g0.y); a1[mi].y = packh2(g0.z, g0.w);
            a1[mi].z = packh2(g1.x, g1.y); a1[mi].w = packh2(g1.z, g1.w);
        }
#pragma unroll
        for (int ni = 0; ni < 8; ni++) {
            const int c0 = wn * 64 + ni * 8 + gid;
            const uint4 bv = B4[c0 * 4 + tig];
#pragma unroll
            for (int mi = 0; mi < 4; mi++) {
                uint32_t af[4], bf[2];
                af[0] = a0[mi].x; af[1] = a1[mi].x;
                af[2] = a0[mi].y; af[3] = a1[mi].y;
                bf[0] = bv.x; bf[1] = bv.y;
                mma_f16(acc[mi][ni], af, bf);
                af[0] = a0[mi].z; af[1] = a1[mi].z;
                af[2] = a0[mi].w; af[3] = a1[mi].w;
                bf[0] = bv.z; bf[1] = bv.w;
                mma_f16(acc[mi][ni], af, bf);
            }
        }
        rb = (rb + 1 == 3) ? 0 : rb + 1;
    }

#pragma unroll
    for (int mi = 0; mi < 4; mi++) {
#pragma unroll
        for (int ni = 0; ni < 8; ni++) {
            const int row0 = rowBase + wm * 64 + mi * 16 + gid;
            const int col  = wn * 64 + ni * 8 + tig * 2;
            *(uint32_t*)&C[(size_t)row0 * N + col] = packh2(acc[mi][ni][0], acc[mi][ni][1]);
            *(uint32_t*)&C[(size_t)(row0 + 8) * N + col] = packh2(acc[mi][ni][2], acc[mi][ni][3]);
        }
    }
}

// ---------------------------------------------------------------------------
// Persistent fp16 GEMM: C = A[M,K] @ BT[N,K]^T (+bias).
// CTA tile 128x128, 4 warps, warp 64x64. 3-stage ring. grid = 296 persistent.
// ---------------------------------------------------------------------------
#define GB32  16
#define GBUFU (128 * GB32)
#define GEMM_SMEM_BYTES (6 * GBUFU * 4)   // 49152

template<bool OUT_HALF>
__global__ void __launch_bounds__(128, 2)
gemm_f16(const __half* __restrict__ A, const __half* __restrict__ BT,
         const float* __restrict__ bias, void* __restrict__ Cv,
         int M, int N, int K)
{
    extern __shared__ uint32_t smem[];

    const int tid  = threadIdx.x;
    const int wid  = tid >> 5;
    const int lane = tid & 31;
    const int gid  = lane >> 2;
    const int tig  = lane & 3;
    const int wm   = wid >> 1;
    const int wn   = wid & 1;

    const int fr = tid >> 2;
    const int fg = tid & 3;
    const uint32_t sBase = smem_u32(smem);
    const int nst = K / 32;
    const int nTX = N / 128;
    const int nTiles = nTX * (M / 128);

    for (int tile = blockIdx.x; tile < nTiles; tile += gridDim.x) {
        const int rowBase = (tile / nTX) * 128;
        const int colBase = (tile % nTX) * 128;

        __syncthreads();   // fence smem reuse across tiles

        float acc[4][8][4];
#pragma unroll
        for (int mi = 0; mi < 4; mi++)
#pragma unroll
            for (int ni = 0; ni < 8; ni++)
#pragma unroll
                for (int r = 0; r < 4; r++) acc[mi][ni][r] = 0.0f;

        auto issue = [&](int st, int sb) {
            const int kt = st * 32;
            const uint32_t ab = sBase + (sb * 2 * GBUFU) * 4;
            const uint32_t bb = ab + GBUFU * 4;
#pragma unroll
            for (int it = 0; it < 4; it++) {
                const int r = fr + 32 * it;
                cp_async16(ab + (r * GB32 + fg * 4) * 4,
                           &A[(size_t)(rowBase + r) * K + kt + fg * 8]);
                cp_async16(bb + (r * GB32 + fg * 4) * 4,
                           &BT[(size_t)(colBase + r) * K + kt + fg * 8]);
            }
            CP_COMMIT();
        };

        issue(0, 0);
        if (nst > 1) issue(1, 1);

        int rb = 0;
        for (int st = 0; st < nst; st++) {
            if (st + 1 < nst) { CP_WAIT(1); } else { CP_WAIT(0); }
            __syncthreads();
            if (st + 2 < nst) issue(st + 2, (rb + 2 >= 3) ? rb - 1 : rb + 2);

            const uint4* A4 = (const uint4*)(smem + rb * 2 * GBUFU);
            const uint4* B4 = (const uint4*)(smem + rb * 2 * GBUFU + GBUFU);

            uint4 a0[4], a1[4];
#pragma unroll
            for (int mi = 0; mi < 4; mi++) {
                const int r0 = wm * 64 + mi * 16 + gid;
                a0[mi] = A4[r0 * 4 + tig];
                a1[mi] = A4[(r0 + 8) * 4 + tig];
            }
#pragma unroll
            for (int ni = 0; ni < 8; ni++) {
                const int c0 = wn * 64 + ni * 8 + gid;
                const uint4 bv = B4[c0 * 4 + tig];
#pragma unroll
                for (int mi = 0; mi < 4; mi++) {
                    uint32_t af[4], bf[2];
                    af[0] = a0[mi].x; af[1] = a1[mi].x;
                    af[2] = a0[mi].y; af[3] = a1[mi].y;
                    bf[0] = bv.x; bf[1] = bv.y;
                    mma_f16(acc[mi][ni], af, bf);
                    af[0] = a0[mi].z; af[1] = a1[mi].z;
                    af[2] = a0[mi].w; af[3] = a1[mi].w;
                    bf[0] = bv.z; bf[1] = bv.w;
                    mma_f16(acc[mi][ni], af, bf);
                }
            }
            rb = (rb + 1 == 3) ? 0 : rb + 1;
        }

#pragma unroll
        for (int mi = 0; mi < 4; mi++) {
#pragma unroll
            for (int ni = 0; ni < 8; ni++) {
                const int row0 = rowBase + wm * 64 + mi * 16 + gid;
                const int col  = colBase + wn * 64 + ni * 8 + tig * 2;
                if (OUT_HALF) {
                    __half* C = (__half*)Cv;
                    *(uint32_t*)&C[(size_t)row0 * N + col] =
                        packh2(acc[mi][ni][0], acc[mi][ni][1]);
                    *(uint32_t*)&C[(size_t)(row0 + 8) * N + col] =
                        packh2(acc[mi][ni][2], acc[mi][ni][3]);
                } else {
                    float* C = (float*)Cv;
                    float b0 = 0.f, b1 = 0.f;
                    if (bias) { b0 = bias[col]; b1 = bias[col + 1]; }
                    float2 v0, v1;
                    v0.x = acc[mi][ni][0] + b0; v0.y = acc[mi][ni][1] + b1;
                    v1.x = acc[mi][ni][2] + b0; v1.y = acc[mi][ni][3] + b1;
                    *(float2*)&C[(size_t)row0 * N + col] = v0;
                    *(float2*)&C[(size_t)(row0 + 8) * N + col] = v1;
                }
            }
        }
    }
}

// ---------------------------------------------------------------------------
// fp16 flash attention; ex2.approx.f16x2 softmax, l via ones-column MMA.
// (proven in R8, unchanged)
// ---------------------------------------------------------------------------
__global__ void __launch_bounds__(256)
attn_f16(const __half* __restrict__ qkv, __half* __restrict__ o_out)
{
    __shared__ uint4    sk4[2][64 * 4];
    __shared__ uint32_t svt[2][32 * 32];

    const int bx = blockIdx.x;
    const int qt = bx & 7;
    const int c  = (bx >> 3) & 3;
    const int h  = (bx >> 5) & 7;
    const int b  = bx >> 8;

    const int tid  = threadIdx.x;
    const int wid  = tid >> 5;
    const int lane = tid & 31;
    const int gid  = lane >> 2;
    const int tig  = lane & 3;

    const size_t rowbase = (size_t)b * NTOK + (size_t)c * BLKTOK;

    const int q0 = qt * 128 + wid * 16;
    uint4 qa0, qa1;
    {
        const __half* qp0 = qkv + (rowbase + q0 + gid) * QKVD + h * HD;
        const __half* qp1 = qkv + (rowbase + q0 + gid + 8) * QKVD + h * HD;
        qa0 = *(const uint4*)(qp0 + 8 * tig);
        qa1 = *(const uint4*)(qp1 + 8 * tig);
    }

    const int keyl = tid >> 2;
    const int dgrp = tid & 3;
    const int d0   = dgrp * 8;

    {
        const __half* kp = qkv + (rowbase + keyl) * QKVD + CDIM + h * HD;
        const uint4 kv = *(const uint4*)(kp + d0);
        const uint4 vv = *(const uint4*)(kp + CDIM + d0);
        sk4[0][keyl * 4 + dgrp] = kv;
        const __half* vh = (const __half*)&vv;
        __half* sv = (__half*)svt[0];
#pragma unroll
        for (int j = 0; j < 8; j++)
            sv[(d0 + j) * 64 + (((keyl >> 1) ^ (j << 2)) << 1) + (keyl & 1)] = vh[j];
    }
    __syncthreads();

    float m0 = -1e30f, m1 = -1e30f;
    float lacc[4];
    float o[4][4];
#pragma unroll
    for (int r = 0; r < 4; r++) lacc[r] = 0.0f;
#pragma unroll
    for (int ni = 0; ni < 4; ni++)
#pragma unroll
        for (int r = 0; r < 4; r++) o[ni][r] = 0.0f;

    const uint32_t ONES = 0x3C003C00u;

    for (int kt = 0; kt < 16; kt++) {
        const int buf = kt & 1;

        uint4 kv, vv;
        if (kt < 15) {
            const __half* kp = qkv + (rowbase + (kt + 1) * 64 + keyl) * QKVD + CDIM + h * HD;
            kv = *(const uint4*)(kp + d0);
            vv = *(const uint4*)(kp + CDIM + d0);
        }

        float s[8][4];
#pragma unroll
        for (int nj = 0; nj < 8; nj++) {
#pragma unroll
            for (int r = 0; r < 4; r++) s[nj][r] = 0.0f;
            const uint4 kb = sk4[buf][(nj * 8 + gid) * 4 + tig];
            uint32_t af[4], bf[2];
            af[0] = qa0.x; af[1] = qa1.x; af[2] = qa0.y; af[3] = qa1.y;
            bf[0] = kb.x;  bf[1] = kb.y;
            mma_f16(s[nj], af, bf);
            af[0] = qa0.z; af[1] = qa1.z; af[2] = qa0.w; af[3] = qa1.w;
            bf[0] = kb.z;  bf[1] = kb.w;
            mma_f16(s[nj], af, bf);
        }

        float tmax0 = -1e30f, tmax1 = -1e30f;
#pragma unroll
        for (int nj = 0; nj < 8; nj++) {
            tmax0 = fmaxf(tmax0, fmaxf(s[nj][0], s[nj][1]));
            tmax1 = fmaxf(tmax1, fmaxf(s[nj][2], s[nj][3]));
        }
        tmax0 = fmaxf(tmax0, __shfl_xor_sync(0xffffffffu, tmax0, 1));
        tmax0 = fmaxf(tmax0, __shfl_xor_sync(0xffffffffu, tmax0, 2));
        tmax1 = fmaxf(tmax1, __shfl_xor_sync(0xffffffffu, tmax1, 1));
        tmax1 = fmaxf(tmax1, __shfl_xor_sync(0xffffffffu, tmax1, 2));

        const float m0n = fmaxf(m0, tmax0);
        const float m1n = fmaxf(m1, tmax1);
        const float a0 = exp2f((m0 - m0n) * C2LOG);
        const float a1 = exp2f((m1 - m1n) * C2LOG);
        m0 = m0n; m1 = m1n;
        const float mc0 = m0 * C2LOG;
        const float mc1 = m1 * C2LOG;

        lacc[0] *= a0; lacc[1] *= a0; lacc[2] *= a1; lacc[3] *= a1;
#pragma unroll
        for (int ni = 0; ni < 4; ni++) {
            o[ni][0] *= a0; o[ni][1] *= a0;
            o[ni][2] *= a1; o[ni][3] *= a1;
        }

        uint32_t pf[8][2];
#pragma unroll
        for (int nj = 0; nj < 8; nj++) {
            const float t0 = fmaf(s[nj][0], C2LOG, -mc0);
            const float t1 = fmaf(s[nj][1], C2LOG, -mc0);
            const float t2 = fmaf(s[nj][2], C2LOG, -mc1);
            const float t3 = fmaf(s[nj][3], C2LOG, -mc1);
            pf[nj][0] = h2ex2(packh2(t0, t1));
            pf[nj][1] = h2ex2(packh2(t2, t3));
        }

        const uint32_t* vb = svt[buf];
#pragma unroll
        for (int t = 0; t < 4; t++) {
            uint32_t af[4];
            af[0] = pf[2 * t][0];
            af[1] = pf[2 * t][1];
            af[2] = pf[2 * t + 1][0];
            af[3] = pf[2 * t + 1][1];
            uint32_t ob[2] = { ONES, ONES };
            mma_f16(lacc, af, ob);
            const int sw = gid << 2;
#pragma unroll
            for (int ni = 0; ni < 4; ni++) {
                const int d = ni * 8 + gid;
                uint32_t bf[2];
                bf[0] = vb[d * 32 + ((8 * t + tig)     ^ sw)];
                bf[1] = vb[d * 32 + ((8 * t + tig + 4) ^ sw)];
                mma_f16(o[ni], af, bf);
            }
        }

        if (kt < 15) {
            const int nb = buf ^ 1;
            sk4[nb][keyl * 4 + dgrp] = kv;
            const __half* vh = (const __half*)&vv;
            __half* sv = (__half*)svt[nb];
#pragma unroll
            for (int j = 0; j < 8; j++)
                sv[(d0 + j) * 64 + (((keyl >> 1) ^ (j << 2)) << 1) + (keyl & 1)] = vh[j];
        }
        __syncthreads();
    }

    const float inv0 = 1.0f / lacc[0];
    const float inv1 = 1.0f / lacc[2];

    __half* op0 = o_out + (rowbase + q0 + gid) * CDIM + h * HD;
    __half* op1 = o_out + (rowbase + q0 + gid + 8) * CDIM + h * HD;
#pragma unroll
    for (int ni = 0; ni < 4; ni++) {
        *(uint32_t*)(op0 + ni * 8 + tig * 2) = packh2(o[ni][0] * inv0, o[ni][1] * inv0);
        *(uint32_t*)(op1 + ni * 8 + tig * 2) = packh2(o[ni][2] * inv1, o[ni][3] * inv1);
    }
}

// ---------------------------------------------------------------------------
// Launch
// ---------------------------------------------------------------------------
extern "C" void kernel_launch(void* const* d_in, const int* in_sizes, int n_in,
                              void* d_out, int out_size)
{
    const float* x    = (const float*)d_in[0];
    const float* Wd   = (const float*)d_in[1];
    const float* Wqkv = (const float*)d_in[2];
    const float* Wup  = (const float*)d_in[3];
    const float* bup  = (const float*)d_in[4];
    float* out = (float*)d_out;

    __half *ph16, *pqkv16, *po16, *pwdT, *pwqkvT, *pwupT;
    cudaGetSymbolAddress((void**)&ph16,   g_h16);
    cudaGetSymbolAddress((void**)&pqkv16, g_qkv16);
    cudaGetSymbolAddress((void**)&po16,   g_o16);
    cudaGetSymbolAddress((void**)&pwdT,   g_wdT);
    cudaGetSymbolAddress((void**)&pwqkvT, g_wqkvT);
    cudaGetSymbolAddress((void**)&pwupT,  g_wupT);

    cudaFuncSetAttribute(gemm1_f16, cudaFuncAttributeMaxDynamicSharedMemorySize,
                         G1_SMEM_BYTES);
    cudaFuncSetAttribute(gemm_f16<true>,
                         cudaFuncAttributeMaxDynamicSharedMemorySize, GEMM_SMEM_BYTES);
    cudaFuncSetAttribute(gemm_f16<false>,
                         cudaFuncAttributeMaxDynamicSharedMemorySize, GEMM_SMEM_BYTES);

    // prologue: fused weight transposes (one launch)
    transpose_all<<<832, dim3(32, 8)>>>(Wd, Wqkv, Wup, pwdT, pwqkvT, pwupT);

    // GEMM1: h16 = x(fp32) @ Wd   — x read once, cvt folded
    gemm1_f16<<<M_TOTAL / 128, 256, G1_SMEM_BYTES>>>(x, pwdT, ph16);

    // GEMM2: qkv16 = h16 @ Wqkv (persistent)
    gemm_f16<true><<<296, 128, GEMM_SMEM_BYTES>>>(ph16, pwqkvT, nullptr, pqkv16,
                                                  M_TOTAL, QKVD, CDIM);
    // attention
    attn_f16<<<BATCH * HEADS * CUT * (BLKTOK / 128), 256>>>(pqkv16, po16);

    // GEMM3: out = o16 @ Wup + bup (persistent, fp32 out)
    gemm_f16<false><<<296, 128, GEMM_SMEM_BYTES>>>(po16, pwupT, bup, out,
                                                   M_TOTAL, INCH, CDIM);
}

// round 10
// speedup vs baseline: 25.3135x; 1.1365x over previous
#include <cuda_runtime.h>
#include <cuda_fp16.h>
#include <stdint.h>
#include <math.h>

// ---------------------------------------------------------------------------
// Problem constants
// ---------------------------------------------------------------------------
#define BATCH   4
#define NTOK    4096
#define INCH    1280
#define CDIM    256
#define QKVD    768
#define HEADS   8
#define HD      32
#define CUT     4
#define BLKTOK  1024
#define M_TOTAL (BATCH*NTOK)
#define SCALE_F 0.07905694150420949f   // 160^-0.5
#define C2LOG   (SCALE_F * 1.4426950408889634f)   // SCALE * log2(e)

// ---------------------------------------------------------------------------
// Scratch
// ---------------------------------------------------------------------------
__device__ __half g_h16[M_TOTAL * CDIM];
__device__ __half g_qkv16[M_TOTAL * QKVD];
__device__ __half g_o16[M_TOTAL * CDIM];
__device__ __half g_wdT[CDIM * INCH];
__device__ __half g_wqkvT[QKVD * CDIM];
__device__ __half g_wupT[INCH * CDIM];

// ---------------------------------------------------------------------------
// helpers
// ---------------------------------------------------------------------------
__device__ __forceinline__ void mma_f16(float* d, const uint32_t* a, const uint32_t* b) {
    asm volatile(
        "mma.sync.aligned.m16n8k16.row.col.f32.f16.f16.f32 "
        "{%0,%1,%2,%3}, {%4,%5,%6,%7}, {%8,%9}, {%0,%1,%2,%3};"
        : "+f"(d[0]), "+f"(d[1]), "+f"(d[2]), "+f"(d[3])
        : "r"(a[0]), "r"(a[1]), "r"(a[2]), "r"(a[3]), "r"(b[0]), "r"(b[1]));
}
__device__ __forceinline__ uint32_t smem_u32(const void* p) {
    uint32_t a;
    asm("{ .reg .u64 t; cvta.to.shared.u64 t, %1; cvt.u32.u64 %0, t; }" : "=r"(a) : "l"(p));
    return a;
}
__device__ __forceinline__ void cp_async16(uint32_t dst, const void* src) {
    asm volatile("cp.async.cg.shared.global [%0], [%1], 16;" :: "r"(dst), "l"(src));
}
#define CP_COMMIT() asm volatile("cp.async.commit_group;" ::: "memory")
#define CP_WAIT(n)  asm volatile("cp.async.wait_group %0;" :: "n"(n) : "memory")

__device__ __forceinline__ uint32_t packh2(float lo, float hi) {
    __half2 h = __floats2half2_rn(lo, hi);
    return *(uint32_t*)&h;
}
__device__ __forceinline__ uint32_t h2ex2(uint32_t h2) {
    uint32_t r;
    asm("ex2.approx.f16x2 %0, %1;" : "=r"(r) : "r"(h2));
    return r;
}
__device__ __forceinline__ void ldmx4t(uint32_t& v0, uint32_t& v1, uint32_t& v2,
                                       uint32_t& v3, uint32_t addr) {
    asm volatile("ldmatrix.sync.aligned.m8n8.x4.trans.shared.b16 {%0,%1,%2,%3}, [%4];"
                 : "=r"(v0), "=r"(v1), "=r"(v2), "=r"(v3) : "r"(addr));
}

// ---------------------------------------------------------------------------
// Fused weight transposes fp32 -> fp16 K-major (one launch, 3 segments)
// ---------------------------------------------------------------------------
__global__ void transpose_all(const float* __restrict__ Wd,
                              const float* __restrict__ Wqkv,
                              const float* __restrict__ Wup,
                              __half* __restrict__ wdT,
                              __half* __restrict__ wqkvT,
                              __half* __restrict__ wupT)
{
    __shared__ float t[32][33];
    const int bx = blockIdx.x;
    const float* W; __half* WT; int K, N, gx, base;
    if (bx < 320)      { W = Wd;   WT = wdT;   K = INCH; N = CDIM; gx = 40; base = 0; }
    else if (bx < 512) { W = Wqkv; WT = wqkvT; K = CDIM; N = QKVD; gx = 8;  base = 320; }
    else               { W = Wup;  WT = wupT;  K = CDIM; N = INCH; gx = 8;  base = 512; }
    const int i = bx - base;
    const int kb = (i % gx) * 32, nb = (i / gx) * 32;
    const int tx = threadIdx.x, ty = threadIdx.y;
#pragma unroll
    for (int r = 0; r < 4; r++)
        t[ty + 8 * r][tx] = W[(size_t)(kb + ty + 8 * r) * N + nb + tx];
    __syncthreads();
#pragma unroll
    for (int r = 0; r < 4; r++)
        WT[(size_t)(nb + ty + 8 * r) * K + kb + tx] = __float2half_rn(t[tx][ty + 8 * r]);
}

// ---------------------------------------------------------------------------
// GEMM1: h16[M,256] = x(fp32)[M,1280] @ WdT(fp16)[256,1280]^T  (proven R9)
// ---------------------------------------------------------------------------
#define A1STRIDE 36
#define A1BUF (128 * A1STRIDE)
#define B1BUF (256 * 16)
#define G1_SMEM_BYTES (3 * (A1BUF + B1BUF) * 4)

__global__ void __launch_bounds__(256, 1)
gemm1_f16(const float* __restrict__ A, const __half* __restrict__ BT,
          __half* __restrict__ C)
{
    extern __shared__ uint32_t smem[];
    float*    As = (float*)smem;
    uint32_t* Bs = smem + 3 * A1BUF;

    const int tid  = threadIdx.x;
    const int wid  = tid >> 5;
    const int lane = tid & 31;
    const int gid  = lane >> 2;
    const int tig  = lane & 3;
    const int wm   = wid >> 2;
    const int wn   = wid & 3;
    const int rowBase = blockIdx.x * 128;
    const int K = INCH, N = CDIM;

    float acc[4][8][4];
#pragma unroll
    for (int mi = 0; mi < 4; mi++)
#pragma unroll
        for (int ni = 0; ni < 8; ni++)
#pragma unroll
            for (int r = 0; r < 4; r++) acc[mi][ni][r] = 0.0f;

    const uint32_t asBase = smem_u32(As);
    const uint32_t bsBase = smem_u32(Bs);
    const int nst = K / 32;

    auto issue = [&](int st, int sb) {
        const int kt = st * 32;
        const uint32_t ab = asBase + (sb * A1BUF) * 4;
        const uint32_t bb = bsBase + (sb * B1BUF) * 4;
#pragma unroll
        for (int it = 0; it < 4; it++) {
            const int ch = tid + 256 * it;
            const int ar = ch >> 3, ag = ch & 7;
            cp_async16(ab + (ar * A1STRIDE + ag * 4) * 4,
                       &A[(size_t)(rowBase + ar) * K + kt + ag * 4]);
            const int br = ch >> 2, bg = ch & 3;
            cp_async16(bb + (br * 16 + bg * 4) * 4,
                       &BT[(size_t)br * K + kt + bg * 8]);
        }
        CP_COMMIT();
    };

    issue(0, 0);
    issue(1, 1);

    int rb = 0;
    for (int st = 0; st < nst; st++) {
        if (st + 1 < nst) { CP_WAIT(1); } else { CP_WAIT(0); }
        __syncthreads();
        if (st + 2 < nst) issue(st + 2, (rb + 2 >= 3) ? rb - 1 : rb + 2);

        const float* Ab = As + rb * A1BUF;
        const uint4* B4 = (const uint4*)(Bs + rb * B1BUF);

        uint4 a0[4], a1[4];
#pragma unroll
        for (int mi = 0; mi < 4; mi++) {
            const int r0 = wm * 64 + mi * 16 + gid;
            const float4 f0 = *(const float4*)(Ab + r0 * A1STRIDE + tig * 8);
            const float4 f1 = *(const float4*)(Ab + r0 * A1STRIDE + tig * 8 + 4);
            const float4 g0 = *(const float4*)(Ab + (r0 + 8) * A1STRIDE + tig * 8);
            const float4 g1 = *(const float4*)(Ab + (r0 + 8) * A1STRIDE + tig * 8 + 4);
            a0[mi].x = packh2(f0.x, f0.y); a0[mi].y = packh2(f0.z, f0.w);
            a0[mi].z = packh2(f1.x, f1.y); a0[mi].w = packh2(f1.z, f1.w);
            a1[mi].x = packh2(g0.x, g0.y); a1[mi].y = packh2(g0.z, g0.w);
            a1[mi].z = packh2(g1.x, g1.y); a1[mi].w = packh2(g1.z, g1.w);
        }
#pragma unroll
        for (int ni = 0; ni < 8; ni++) {
            const int c0 = wn * 64 + ni * 8 + gid;
            const uint4 bv = B4[c0 * 4 + tig];
#pragma unroll
            for (int mi = 0; mi < 4; mi++) {
                uint32_t af[4], bf[2];
                af[0] = a0[mi].x; af[1] = a1[mi].x;
                af[2] = a0[mi].y; af[3] = a1[mi].y;
                bf[0] = bv.x; bf[1] = bv.y;
                mma_f16(acc[mi][ni], af, bf);
                af[0] = a0[mi].z; af[1] = a1[mi].z;
                af[2] = a0[mi].w; af[3] = a1[mi].w;
                bf[0] = bv.z; bf[1] = bv.w;
                mma_f16(acc[mi][ni], af, bf);
            }
        }
        rb = (rb + 1 == 3) ? 0 : rb + 1;
    }

#pragma unroll
    for (int mi = 0; mi < 4; mi++) {
#pragma unroll
        for (int ni = 0; ni < 8; ni++) {
            const int row0 = rowBase + wm * 64 + mi * 16 + gid;
            const int col  = wn * 64 + ni * 8 + tig * 2;
            *(uint32_t*)&C[(size_t)row0 * N + col] = packh2(acc[mi][ni][0], acc[mi][ni][1]);
            *(uint32_t*)&C[(size_t)(row0 + 8) * N + col] = packh2(acc[mi][ni][2], acc[mi][ni][3]);
        }
    }
}

// ---------------------------------------------------------------------------
// Persistent fp16 GEMM (proven R9)
// ---------------------------------------------------------------------------
#define GB32  16
#define GBUFU (128 * GB32)
#define GEMM_SMEM_BYTES (6 * GBUFU * 4)

template<bool OUT_HALF>
__global__ void __launch_bounds__(128, 2)
gemm_f16(const __half* __restrict__ A, const __half* __restrict__ BT,
         const float* __restrict__ bias, void* __restrict__ Cv,
         int M, int N, int K)
{
    extern __shared__ uint32_t smem[];

    const int tid  = threadIdx.x;
    const int wid  = tid >> 5;
    const int lane = tid & 31;
    const int gid  = lane >> 2;
    const int tig  = lane & 3;
    const int wm   = wid >> 1;
    const int wn   = wid & 1;

    const int fr = tid >> 2;
    const int fg = tid & 3;
    const uint32_t sBase = smem_u32(smem);
    const int nst = K / 32;
    const int nTX = N / 128;
    const int nTiles = nTX * (M / 128);

    for (int tile = blockIdx.x; tile < nTiles; tile += gridDim.x) {
        const int rowBase = (tile / nTX) * 128;
        const int colBase = (tile % nTX) * 128;

        __syncthreads();

        float acc[4][8][4];
#pragma unroll
        for (int mi = 0; mi < 4; mi++)
#pragma unroll
            for (int ni = 0; ni < 8; ni++)
#pragma unroll
                for (int r = 0; r < 4; r++) acc[mi][ni][r] = 0.0f;

        auto issue = [&](int st, int sb) {
            const int kt = st * 32;
            const uint32_t ab = sBase + (sb * 2 * GBUFU) * 4;
            const uint32_t bb = ab + GBUFU * 4;
#pragma unroll
            for (int it = 0; it < 4; it++) {
                const int r = fr + 32 * it;
                cp_async16(ab + (r * GB32 + fg * 4) * 4,
                           &A[(size_t)(rowBase + r) * K + kt + fg * 8]);
                cp_async16(bb + (r * GB32 + fg * 4) * 4,
                           &BT[(size_t)(colBase + r) * K + kt + fg * 8]);
            }
            CP_COMMIT();
        };

        issue(0, 0);
        if (nst > 1) issue(1, 1);

        int rb = 0;
        for (int st = 0; st < nst; st++) {
            if (st + 1 < nst) { CP_WAIT(1); } else { CP_WAIT(0); }
            __syncthreads();
            if (st + 2 < nst) issue(st + 2, (rb + 2 >= 3) ? rb - 1 : rb + 2);

            const uint4* A4 = (const uint4*)(smem + rb * 2 * GBUFU);
            const uint4* B4 = (const uint4*)(smem + rb * 2 * GBUFU + GBUFU);

            uint4 a0[4], a1[4];
#pragma unroll
            for (int mi = 0; mi < 4; mi++) {
                const int r0 = wm * 64 + mi * 16 + gid;
                a0[mi] = A4[r0 * 4 + tig];
                a1[mi] = A4[(r0 + 8) * 4 + tig];
            }
#pragma unroll
            for (int ni = 0; ni < 8; ni++) {
                const int c0 = wn * 64 + ni * 8 + gid;
                const uint4 bv = B4[c0 * 4 + tig];
#pragma unroll
                for (int mi = 0; mi < 4; mi++) {
                    uint32_t af[4], bf[2];
                    af[0] = a0[mi].x; af[1] = a1[mi].x;
                    af[2] = a0[mi].y; af[3] = a1[mi].y;
                    bf[0] = bv.x; bf[1] = bv.y;
                    mma_f16(acc[mi][ni], af, bf);
                    af[0] = a0[mi].z; af[1] = a1[mi].z;
                    af[2] = a0[mi].w; af[3] = a1[mi].w;
                    bf[0] = bv.z; bf[1] = bv.w;
                    mma_f16(acc[mi][ni], af, bf);
                }
            }
            rb = (rb + 1 == 3) ? 0 : rb + 1;
        }

#pragma unroll
        for (int mi = 0; mi < 4; mi++) {
#pragma unroll
            for (int ni = 0; ni < 8; ni++) {
                const int row0 = rowBase + wm * 64 + mi * 16 + gid;
                const int col  = colBase + wn * 64 + ni * 8 + tig * 2;
                if (OUT_HALF) {
                    __half* C = (__half*)Cv;
                    *(uint32_t*)&C[(size_t)row0 * N + col] =
                        packh2(acc[mi][ni][0], acc[mi][ni][1]);
                    *(uint32_t*)&C[(size_t)(row0 + 8) * N + col] =
                        packh2(acc[mi][ni][2], acc[mi][ni][3]);
                } else {
                    float* C = (float*)Cv;
                    float b0 = 0.f, b1 = 0.f;
                    if (bias) { b0 = bias[col]; b1 = bias[col + 1]; }
                    float2 v0, v1;
                    v0.x = acc[mi][ni][0] + b0; v0.y = acc[mi][ni][1] + b1;
                    v1.x = acc[mi][ni][2] + b0; v1.y = acc[mi][ni][3] + b1;
                    *(float2*)&C[(size_t)row0 * N + col] = v0;
                    *(float2*)&C[(size_t)(row0 + 8) * N + col] = v1;
                }
            }
        }
    }
}

// ---------------------------------------------------------------------------
// fp16 flash attention v3: 4 warps x 32 q rows (2 m-tiles/warp), cp.async
// 3-stage ring K/V staging, V natural + swizzled, ldmatrix.x4.trans B-frags.
// K smem granule = key*4 + dgrp; V granule = key*4 + (chunk ^ ((key>>1)&3)).
// Grid = 1024 CTAs, 128 threads, 2 CTA/SM.
// ---------------------------------------------------------------------------
__global__ void __launch_bounds__(128, 2)
attn_f16(const __half* __restrict__ qkv, __half* __restrict__ o_out)
{
    __shared__ uint4 sk4[3][256];
    __shared__ uint4 sv4[3][256];

    const int bx = blockIdx.x;
    const int qt = bx & 7;
    const int c  = (bx >> 3) & 3;
    const int h  = (bx >> 5) & 7;
    const int b  = bx >> 8;

    const int tid  = threadIdx.x;
    const int wid  = tid >> 5;
    const int lane = tid & 31;
    const int gid  = lane >> 2;
    const int tig  = lane & 3;

    const size_t rowbase = (size_t)b * NTOK + (size_t)c * BLKTOK;
    const int q0 = qt * 128 + wid * 32;

    // ---- Q fragments for 2 m-tiles
    uint4 qa[2][2];
#pragma unroll
    for (int mt = 0; mt < 2; mt++) {
        const __half* qp0 = qkv + (rowbase + q0 + mt * 16 + gid) * QKVD + h * HD;
        const __half* qp1 = qkv + (rowbase + q0 + mt * 16 + gid + 8) * QKVD + h * HD;
        qa[mt][0] = *(const uint4*)(qp0 + 8 * tig);
        qa[mt][1] = *(const uint4*)(qp1 + 8 * tig);
    }

    // ldmatrix per-lane base: key0 in 0..15, csel picks chunk parity
    const int key0 = ((lane >> 3) & 1) * 8 + (lane & 7);
    const int csw  = (key0 >> 1) & 3;
    const int csel = (lane >> 4) & 1;

    const uint32_t skaddr = smem_u32(sk4);
    const uint32_t svaddr = smem_u32(sv4);

    auto issue = [&](int t, int sb) {
#pragma unroll
        for (int it = 0; it < 2; it++) {
            const int idx = tid + 128 * it;
            const int k = idx >> 2, g = idx & 3;
            const __half* base = qkv + (rowbase + t * 64 + k) * QKVD + CDIM + h * HD;
            cp_async16(skaddr + (sb * 256 + k * 4 + g) * 16, base + g * 8);
            cp_async16(svaddr + (sb * 256 + k * 4 + (g ^ ((k >> 1) & 3))) * 16,
                       base + CDIM + g * 8);
        }
        CP_COMMIT();
    };

    issue(0, 0);
    issue(1, 1);

    float m[2][2];
    float lacc[2][4];
    float o[2][4][4];
#pragma unroll
    for (int mt = 0; mt < 2; mt++) {
        m[mt][0] = -1e30f; m[mt][1] = -1e30f;
#pragma unroll
        for (int r = 0; r < 4; r++) lacc[mt][r] = 0.0f;
#pragma unroll
        for (int ni = 0; ni < 4; ni++)
#pragma unroll
            for (int r = 0; r < 4; r++) o[mt][ni][r] = 0.0f;
    }

    const uint32_t ONES = 0x3C003C00u;

    int rb = 0;
    for (int kt = 0; kt < 16; kt++) {
        if (kt + 1 < 16) { CP_WAIT(1); } else { CP_WAIT(0); }
        __syncthreads();
        if (kt + 2 < 16) issue(kt + 2, (rb + 2 >= 3) ? rb - 1 : rb + 2);

        // ---- K fragments once, reused by both m-tiles
        uint4 kb[8];
#pragma unroll
        for (int nj = 0; nj < 8; nj++)
            kb[nj] = sk4[rb][(nj * 8 + gid) * 4 + tig];

        uint32_t pf[2][8][2];
#pragma unroll
        for (int mt = 0; mt < 2; mt++) {
            float s[8][4];
#pragma unroll
            for (int nj = 0; nj < 8; nj++) {
#pragma unroll
                for (int r = 0; r < 4; r++) s[nj][r] = 0.0f;
                uint32_t af[4], bf[2];
                af[0] = qa[mt][0].x; af[1] = qa[mt][1].x;
                af[2] = qa[mt][0].y; af[3] = qa[mt][1].y;
                bf[0] = kb[nj].x; bf[1] = kb[nj].y;
                mma_f16(s[nj], af, bf);
                af[0] = qa[mt][0].z; af[1] = qa[mt][1].z;
                af[2] = qa[mt][0].w; af[3] = qa[mt][1].w;
                bf[0] = kb[nj].z; bf[1] = kb[nj].w;
                mma_f16(s[nj], af, bf);
            }

            float tmax0 = -1e30f, tmax1 = -1e30f;
#pragma unroll
            for (int nj = 0; nj < 8; nj++) {
                tmax0 = fmaxf(tmax0, fmaxf(s[nj][0], s[nj][1]));
                tmax1 = fmaxf(tmax1, fmaxf(s[nj][2], s[nj][3]));
            }
            tmax0 = fmaxf(tmax0, __shfl_xor_sync(0xffffffffu, tmax0, 1));
            tmax0 = fmaxf(tmax0, __shfl_xor_sync(0xffffffffu, tmax0, 2));
            tmax1 = fmaxf(tmax1, __shfl_xor_sync(0xffffffffu, tmax1, 1));
            tmax1 = fmaxf(tmax1, __shfl_xor_sync(0xffffffffu, tmax1, 2));

            const float m0n = fmaxf(m[mt][0], tmax0);
            const float m1n = fmaxf(m[mt][1], tmax1);
            const float a0 = exp2f((m[mt][0] - m0n) * C2LOG);
            const float a1 = exp2f((m[mt][1] - m1n) * C2LOG);
            m[mt][0] = m0n; m[mt][1] = m1n;
            const float mc0 = m0n * C2LOG;
            const float mc1 = m1n * C2LOG;

            lacc[mt][0] *= a0; lacc[mt][1] *= a0;
            lacc[mt][2] *= a1; lacc[mt][3] *= a1;
#pragma unroll
            for (int ni = 0; ni < 4; ni++) {
                o[mt][ni][0] *= a0; o[mt][ni][1] *= a0;
                o[mt][ni][2] *= a1; o[mt][ni][3] *= a1;
            }

#pragma unroll
            for (int nj = 0; nj < 8; nj++) {
                const float t0 = fmaf(s[nj][0], C2LOG, -mc0);
                const float t1 = fmaf(s[nj][1], C2LOG, -mc0);
                const float t2 = fmaf(s[nj][2], C2LOG, -mc1);
                const float t3 = fmaf(s[nj][3], C2LOG, -mc1);
                pf[mt][nj][0] = h2ex2(packh2(t0, t1));
                pf[mt][nj][1] = h2ex2(packh2(t2, t3));
            }
        }

        // ---- O += P @ V (ldmatrix.x4.trans B-frags, shared across m-tiles)
        const uint32_t vbase = svaddr + rb * 4096 + key0 * 64;
#pragma unroll
        for (int t = 0; t < 4; t++) {
            uint32_t af[2][4];
#pragma unroll
            for (int mt = 0; mt < 2; mt++) {
                af[mt][0] = pf[mt][2 * t][0];
                af[mt][1] = pf[mt][2 * t][1];
                af[mt][2] = pf[mt][2 * t + 1][0];
                af[mt][3] = pf[mt][2 * t + 1][1];
            }
            uint32_t ob[2] = { ONES, ONES };
            mma_f16(lacc[0], af[0], ob);
            mma_f16(lacc[1], af[1], ob);
#pragma unroll
            for (int dh = 0; dh < 2; dh++) {
                uint32_t v0, v1, v2, v3;
                const uint32_t addr = vbase + t * 1024 + (((dh * 2 + csel) ^ csw) * 16);
                ldmx4t(v0, v1, v2, v3, addr);
                uint32_t bf0[2] = { v0, v1 };
                uint32_t bf1[2] = { v2, v3 };
#pragma unroll
                for (int mt = 0; mt < 2; mt++) {
                    mma_f16(o[mt][dh * 2],     af[mt], bf0);
                    mma_f16(o[mt][dh * 2 + 1], af[mt], bf1);
                }
            }
        }
        rb = (rb + 1 == 3) ? 0 : rb + 1;
    }

    // ---- finalize both m-tiles
#pragma unroll
    for (int mt = 0; mt < 2; mt++) {
        const float inv0 = 1.0f / lacc[mt][0];
        const float inv1 = 1.0f / lacc[mt][2];
        __half* op0 = o_out + (rowbase + q0 + mt * 16 + gid) * CDIM + h * HD;
        __half* op1 = o_out + (rowbase + q0 + mt * 16 + gid + 8) * CDIM + h * HD;
#pragma unroll
        for (int ni = 0; ni < 4; ni++) {
            *(uint32_t*)(op0 + ni * 8 + tig * 2) =
                packh2(o[mt][ni][0] * inv0, o[mt][ni][1] * inv0);
            *(uint32_t*)(op1 + ni * 8 + tig * 2) =
                packh2(o[mt][ni][2] * inv1, o[mt][ni][3] * inv1);
        }
    }
}

// ---------------------------------------------------------------------------
// Launch
// ---------------------------------------------------------------------------
extern "C" void kernel_launch(void* const* d_in, const int* in_sizes, int n_in,
                              void* d_out, int out_size)
{
    const float* x    = (const float*)d_in[0];
    const float* Wd   = (const float*)d_in[1];
    const float* Wqkv = (const float*)d_in[2];
    const float* Wup  = (const float*)d_in[3];
    const float* bup  = (const float*)d_in[4];
    float* out = (float*)d_out;

    __half *ph16, *pqkv16, *po16, *pwdT, *pwqkvT, *pwupT;
    cudaGetSymbolAddress((void**)&ph16,   g_h16);
    cudaGetSymbolAddress((void**)&pqkv16, g_qkv16);
    cudaGetSymbolAddress((void**)&po16,   g_o16);
    cudaGetSymbolAddress((void**)&pwdT,   g_wdT);
    cudaGetSymbolAddress((void**)&pwqkvT, g_wqkvT);
    cudaGetSymbolAddress((void**)&pwupT,  g_wupT);

    cudaFuncSetAttribute(gemm1_f16, cudaFuncAttributeMaxDynamicSharedMemorySize,
                         G1_SMEM_BYTES);
    cudaFuncSetAttribute(gemm_f16<true>,
                         cudaFuncAttributeMaxDynamicSharedMemorySize, GEMM_SMEM_BYTES);
    cudaFuncSetAttribute(gemm_f16<false>,
                         cudaFuncAttributeMaxDynamicSharedMemorySize, GEMM_SMEM_BYTES);

    transpose_all<<<832, dim3(32, 8)>>>(Wd, Wqkv, Wup, pwdT, pwqkvT, pwupT);

    gemm1_f16<<<M_TOTAL / 128, 256, G1_SMEM_BYTES>>>(x, pwdT, ph16);

    gemm_f16<true><<<296, 128, GEMM_SMEM_BYTES>>>(ph16, pwqkvT, nullptr, pqkv16,
                                                  M_TOTAL, QKVD, CDIM);

    attn_f16<<<BATCH * HEADS * CUT * (BLKTOK / 128), 128>>>(pqkv16, po16);

    gemm_f16<false><<<296, 128, GEMM_SMEM_BYTES>>>(po16, pwupT, bup, out,
                                                   M_TOTAL, INCH, CDIM);
}